// round 15
// baseline (speedup 1.0000x reference)
#include <cuda_runtime.h>
#include <cuda_fp16.h>
#include <math.h>

// ---------------- problem constants ----------------
#define S_LEN   2048
#define D_MODEL 4096
#define H_M     128
#define P_M     64
#define G_M     8
#define N_M     128
#define K_CONV  4
#define CHUNK   128
#define NCHUNK  (S_LEN / CHUNK)          // 16
#define D_INNER (H_M * P_M)              // 8192
#define GN      (G_M * N_M)              // 1024
#define CONV_DIM (D_INNER + 2 * GN)      // 10240
#define PROJ_DIM (D_INNER + CONV_DIM + H_M) // 18560 = 145*128
#define EPS_F   1e-5f

// ---------------- scratch (device globals, no allocation) ----------------
__device__ float g_proj[(size_t)S_LEN * PROJ_DIM];
__device__ float g_conv[(size_t)S_LEN * CONV_DIM];
__device__ float g_dt[(size_t)S_LEN * H_M];
__device__ float g_a[(size_t)S_LEN * H_M];
__device__ float g_Acs[(size_t)NCHUNK * H_M * CHUNK];
__device__ float g_cs[(size_t)NCHUNK * H_M];
__device__ float g_states[(size_t)NCHUNK * H_M * P_M * N_M];
__device__ float g_prev[(size_t)NCHUNK * H_M * P_M * N_M];
__device__ float g_y[(size_t)S_LEN * D_INNER];
// fp16 operands for tensor-core GEMMs (single-term A and W)
__device__ __half g_ah[(size_t)S_LEN * 8192];
__device__ __half g_wh[(size_t)PROJ_DIM * 4096];

// ---------------- small helpers ----------------
__device__ __forceinline__ float siluf(float v) { return v / (1.f + expf(-v)); }
__device__ __forceinline__ float softplusf(float v) { return (v > 20.f) ? v : log1pf(expf(v)); }

__device__ __forceinline__ unsigned smem_u32(const void* p) {
    unsigned a;
    asm("{ .reg .u64 t; cvta.to.shared.u64 t, %1; cvt.u32.u64 %0, t; }" : "=r"(a) : "l"(p));
    return a;
}
__device__ __forceinline__ void cpa(unsigned s, const void* g) {
    asm volatile("cp.async.cg.shared.global [%0], [%1], 16;" :: "r"(s), "l"(g));
}
__device__ __forceinline__ void ldsm4(unsigned addr, unsigned* r) {
    asm volatile("ldmatrix.sync.aligned.m8n8.x4.shared.b16 {%0,%1,%2,%3}, [%4];"
                 : "=r"(r[0]), "=r"(r[1]), "=r"(r[2]), "=r"(r[3]) : "r"(addr));
}
#define MMA_F16(acc, a, b0v, b1v)                                              \
    asm volatile("mma.sync.aligned.m16n8k16.row.col.f32.f16.f16.f32 "          \
                 "{%0,%1,%2,%3}, {%4,%5,%6,%7}, {%8,%9}, {%0,%1,%2,%3};"       \
                 : "+f"((acc)[0]), "+f"((acc)[1]), "+f"((acc)[2]), "+f"((acc)[3]) \
                 : "r"((a)[0]), "r"((a)[1]), "r"((a)[2]), "r"((a)[3]),         \
                   "r"(b0v), "r"(b1v))

// swizzled smem byte offset, 64B rows (32 halves)
__device__ __forceinline__ unsigned swz(int row, int c) {
    return (unsigned)(row * 64 + ((c ^ ((row >> 1) & 3)) << 4));
}
// swizzled smem byte offset, 256B rows (128 halves), ch = 16B chunk 0..15
__device__ __forceinline__ unsigned swz2(int row, int ch) {
    return (unsigned)(row * 256 + ((ch ^ (row & 7)) << 4));
}
__device__ __forceinline__ void sts16v(unsigned addr, const unsigned* v) {
    asm volatile("st.shared.v4.b32 [%0], {%1,%2,%3,%4};"
                 :: "r"(addr), "r"(v[0]), "r"(v[1]), "r"(v[2]), "r"(v[3]));
}
__device__ __forceinline__ void sts32(unsigned addr, unsigned v) {
    asm volatile("st.shared.b32 [%0], %1;" :: "r"(addr), "r"(v));
}
__device__ __forceinline__ void sts16(unsigned addr, unsigned short v) {
    asm volatile("st.shared.b16 [%0], %1;" :: "r"(addr), "h"(v));
}
__device__ __forceinline__ unsigned packh2(__half a, __half b) {
    __half2 h = __halves2half2(a, b);
    return *reinterpret_cast<unsigned*>(&h);
}
__device__ __forceinline__ void cvt8(const float* s, unsigned* hi, unsigned* lo) {
#pragma unroll
    for (int k = 0; k < 4; k++) {
        float a = s[2 * k], b = s[2 * k + 1];
        __half ha = __float2half_rn(a), hb = __float2half_rn(b);
        __half la = __float2half_rn(a - __half2float(ha));
        __half lb = __float2half_rn(b - __half2float(hb));
        hi[k] = packh2(ha, hb);
        lo[k] = packh2(la, lb);
    }
}

// ---------------- fp32 -> fp16 weight conversion (8 elem/thread, 16B store) ----------------
__global__ __launch_bounds__(256) void kCvtW(const float* __restrict__ W) {
    size_t idx = ((size_t)blockIdx.x * 256 + threadIdx.x) * 8;
    float4 a = *reinterpret_cast<const float4*>(W + idx);
    float4 b = *reinterpret_cast<const float4*>(W + idx + 4);
    uint4 o;
    o.x = packh2(__float2half_rn(a.x), __float2half_rn(a.y));
    o.y = packh2(__float2half_rn(a.z), __float2half_rn(a.w));
    o.z = packh2(__float2half_rn(b.x), __float2half_rn(b.y));
    o.w = packh2(__float2half_rn(b.z), __float2half_rn(b.w));
    *reinterpret_cast<uint4*>(g_wh + idx) = o;
}

// ---------------- mma.sync GEMM: C[M,N] = A[M,K] * W[N,K]^T (+resid) ----------------
// CTA tile 256x128, 8 warps of 64x64, BK=32, 4-stage cp.async, single fp16 term.
#define STGB 24576u
#define SMEM_MMA (4u * STGB)

template <int KD, int ND, bool OUTPROJ>
__global__ __launch_bounds__(256, 1) void gemm_mma(float* __restrict__ outp,
                                                   const float* __restrict__ resid) {
    extern __shared__ char smem[];
    const unsigned sb = smem_u32(smem);
    const int tid = threadIdx.x, lane = tid & 31, wid = tid >> 5;
    const int wm = (wid & 3) << 6;
    const int wn = (wid >> 2) << 6;
    const int row0 = blockIdx.x * 256, col0 = blockIdx.y * 128;
    float* C = OUTPROJ ? outp : g_proj;
    constexpr int NKT = KD / 32;

    float acc[4][8][4];
#pragma unroll
    for (int i = 0; i < 4; i++)
#pragma unroll
        for (int j = 0; j < 8; j++)
#pragma unroll
            for (int q = 0; q < 4; q++) acc[i][j][q] = 0.f;

    const int lr = tid >> 2, lc = tid & 3;
    const __half* gA = g_ah + (size_t)(row0 + lr) * KD + lc * 8;
    const __half* gW = g_wh + (size_t)(col0 + lr) * KD + lc * 8;

    auto issue = [&](int kt) {
        unsigned so = sb + (unsigned)(kt & 3) * STGB;
        size_t ko = (size_t)kt * 32;
#pragma unroll
        for (int j = 0; j < 4; j++) {
            unsigned sw = swz(lr + 64 * j, lc);
            cpa(so + sw, gA + (size_t)(64 * j) * KD + ko);
        }
#pragma unroll
        for (int j = 0; j < 2; j++) {
            unsigned sw = swz(lr + 64 * j, lc);
            cpa(so + 16384u + sw, gW + (size_t)(64 * j) * KD + ko);
        }
    };

    issue(0); asm volatile("cp.async.commit_group;" ::: "memory");
    issue(1); asm volatile("cp.async.commit_group;" ::: "memory");
    issue(2); asm volatile("cp.async.commit_group;" ::: "memory");

    const int arow = wm + (lane & 15);
    const int brow = wn + (lane & 15);
    const int chhi = lane >> 4;

    for (int kt = 0; kt < NKT; kt++) {
        asm volatile("cp.async.wait_group 2;" ::: "memory");
        __syncthreads();
        if (kt + 3 < NKT) issue(kt + 3);
        asm volatile("cp.async.commit_group;" ::: "memory");
        unsigned so = sb + (unsigned)(kt & 3) * STGB;
#pragma unroll
        for (int s = 0; s < 2; s++) {
            int chunk = s * 2 + chhi;
            unsigned ah[4][4], bw[4][4];
#pragma unroll
            for (int mi = 0; mi < 4; mi++)
                ldsm4(so + swz(arow + mi * 16, chunk), ah[mi]);
#pragma unroll
            for (int np = 0; np < 4; np++)
                ldsm4(so + 16384u + swz(brow + np * 16, chunk), bw[np]);
#pragma unroll
            for (int mi = 0; mi < 4; mi++)
#pragma unroll
                for (int ni = 0; ni < 8; ni++) {
                    int np = ni >> 1, sr = ni & 1;
                    MMA_F16(acc[mi][ni], ah[mi], bw[np][sr], bw[np][sr + 2]);
                }
        }
    }

#pragma unroll
    for (int mi = 0; mi < 4; mi++) {
        int r = row0 + wm + mi * 16 + (lane >> 2);
#pragma unroll
        for (int ni = 0; ni < 8; ni++) {
            int c = col0 + wn + ni * 8 + ((lane & 3) << 1);
            float2 v0 = make_float2(acc[mi][ni][0], acc[mi][ni][1]);
            float2 v1 = make_float2(acc[mi][ni][2], acc[mi][ni][3]);
            if (OUTPROJ) {
                const float2 r0 = *reinterpret_cast<const float2*>(resid + (size_t)r * ND + c);
                const float2 r1 = *reinterpret_cast<const float2*>(resid + (size_t)(r + 8) * ND + c);
                v0.x += r0.x; v0.y += r0.y; v1.x += r1.x; v1.y += r1.y;
            }
            *reinterpret_cast<float2*>(C + (size_t)r * ND + c) = v0;
            *reinterpret_cast<float2*>(C + (size_t)(r + 8) * ND + c) = v1;
        }
    }
}

// ---------------- fused M + Y_diag (tensor cores + FMUL-chain L) ----------------
#define SMY_ACS 0u
#define SMY_P   512u
#define SMY_L   1024u
#define SMY_CHI 68608u
#define SMY_CLO (SMY_CHI + 32768u)
#define SMY_BHI (SMY_CLO + 32768u)
#define SMY_BLO (SMY_BHI + 32768u)
#define SMY_TOTAL (SMY_BLO + 32768u)
#define SMY_MHI SMY_CHI
#define SMY_MLO SMY_CLO
#define SMY_HHI SMY_BHI
#define SMY_HLO (SMY_BHI + 16384u)

__global__ __launch_bounds__(256, 1) void kMY(const float* __restrict__ Dp) {
    extern __shared__ char smy[];
    const unsigned sb = smem_u32(smy);
    const int h = blockIdx.x, c = blockIdx.y, g = h >> 4;
    const int tid = threadIdx.x, lane = tid & 31, wid = tid >> 5;

    float* acs  = reinterpret_cast<float*>(smy + SMY_ACS);
    float* pdec = reinterpret_cast<float*>(smy + SMY_P);
    float* Ls   = reinterpret_cast<float*>(smy + SMY_L);

    const float* Cg = g_conv + (size_t)(c * 128) * CONV_DIM + D_INNER + GN + g * 128;
    const float* Bg = g_conv + (size_t)(c * 128) * CONV_DIM + D_INNER + g * 128;
#pragma unroll
    for (int it = 0; it < 8; it++) {
        int q = tid + it * 256;
        int row = q >> 4, ch = q & 15;
        float tmp[8];
        unsigned hi[4], lo[4];
        {
            const float4* cs = reinterpret_cast<const float4*>(Cg + (size_t)row * CONV_DIM + ch * 8);
            float4 a = cs[0], b = cs[1];
            tmp[0]=a.x; tmp[1]=a.y; tmp[2]=a.z; tmp[3]=a.w; tmp[4]=b.x; tmp[5]=b.y; tmp[6]=b.z; tmp[7]=b.w;
            cvt8(tmp, hi, lo);
            sts16v(sb + SMY_CHI + swz2(row, ch), hi);
            sts16v(sb + SMY_CLO + swz2(row, ch), lo);
        }
        {
            const float4* bs = reinterpret_cast<const float4*>(Bg + (size_t)row * CONV_DIM + ch * 8);
            float4 a = bs[0], b = bs[1];
            tmp[0]=a.x; tmp[1]=a.y; tmp[2]=a.z; tmp[3]=a.w; tmp[4]=b.x; tmp[5]=b.y; tmp[6]=b.z; tmp[7]=b.w;
            cvt8(tmp, hi, lo);
            sts16v(sb + SMY_BHI + swz2(row, ch), hi);
            sts16v(sb + SMY_BLO + swz2(row, ch), lo);
        }
    }
    if (tid < 128) {
        acs[tid]  = g_Acs[((size_t)(c * 128 + h)) * 128 + tid];
        pdec[tid] = expf(g_a[(size_t)(c * 128 + tid) * H_M + h]);
    }
    __syncthreads();

    if (tid < 128) {
        int i = tid;
        float* Lr = Ls + i * 132;
        for (int j = i + 1; j < 128; j++) Lr[j] = 0.f;
        float v = 1.f;
        Lr[i] = 1.f;
        for (int j = i - 1; j >= 0; j--) { v *= pdec[j + 1]; Lr[j] = v; }
    }

    const int wm  = (wid & 3) << 5;
    const int wn  = (wid >> 2) << 6;
    const int arow = wm + (lane & 15);
    const int brow = wn + (lane & 15);
    const int chhi = lane >> 4;
    float acc[2][8][4];
#pragma unroll
    for (int i = 0; i < 2; i++)
#pragma unroll
        for (int j = 0; j < 8; j++)
#pragma unroll
            for (int q = 0; q < 4; q++) acc[i][j][q] = 0.f;

#pragma unroll
    for (int kc = 0; kc < 8; kc++) {
        int chunk = kc * 2 + chhi;
        unsigned ah[2][4], al_[2][4], bh[4][4], bl[4][4];
#pragma unroll
        for (int mi = 0; mi < 2; mi++) {
            ldsm4(sb + SMY_CHI + swz2(arow + mi * 16, chunk), ah[mi]);
            ldsm4(sb + SMY_CLO + swz2(arow + mi * 16, chunk), al_[mi]);
        }
#pragma unroll
        for (int np = 0; np < 4; np++) {
            ldsm4(sb + SMY_BHI + swz2(brow + np * 16, chunk), bh[np]);
            ldsm4(sb + SMY_BLO + swz2(brow + np * 16, chunk), bl[np]);
        }
#pragma unroll
        for (int mi = 0; mi < 2; mi++)
#pragma unroll
            for (int ni = 0; ni < 8; ni++) {
                int np = ni >> 1, sr = ni & 1;
                MMA_F16(acc[mi][ni], ah[mi], bh[np][sr], bh[np][sr + 2]);
            }
#pragma unroll
        for (int mi = 0; mi < 2; mi++)
#pragma unroll
            for (int ni = 0; ni < 8; ni++) {
                int np = ni >> 1, sr = ni & 1;
                MMA_F16(acc[mi][ni], ah[mi], bl[np][sr], bl[np][sr + 2]);
            }
#pragma unroll
        for (int mi = 0; mi < 2; mi++)
#pragma unroll
            for (int ni = 0; ni < 8; ni++) {
                int np = ni >> 1, sr = ni & 1;
                MMA_F16(acc[mi][ni], al_[mi], bh[np][sr], bh[np][sr + 2]);
            }
    }
    __syncthreads();

#pragma unroll
    for (int mi = 0; mi < 2; mi++) {
#pragma unroll
        for (int ni = 0; ni < 8; ni++) {
            int r0 = wm + mi * 16 + (lane >> 2);
            int cj = wn + ni * 8 + ((lane & 3) << 1);
            const float* L0 = Ls + r0 * 132 + cj;
            const float* L1 = Ls + (r0 + 8) * 132 + cj;
            float m0 = acc[mi][ni][0] * L0[0];
            float m1 = acc[mi][ni][1] * L0[1];
            float m2 = acc[mi][ni][2] * L1[0];
            float m3 = acc[mi][ni][3] * L1[1];
            __half h0 = __float2half_rn(m0), h1 = __float2half_rn(m1);
            __half h2 = __float2half_rn(m2), h3 = __float2half_rn(m3);
            __half e0 = __float2half_rn(m0 - __half2float(h0));
            __half e1 = __float2half_rn(m1 - __half2float(h1));
            __half e2 = __float2half_rn(m2 - __half2float(h2));
            __half e3 = __float2half_rn(m3 - __half2float(h3));
            unsigned off0 = swz2(r0, cj >> 3) + (cj & 7) * 2;
            unsigned off1 = swz2(r0 + 8, cj >> 3) + (cj & 7) * 2;
            sts32(sb + SMY_MHI + off0, packh2(h0, h1));
            sts32(sb + SMY_MLO + off0, packh2(e0, e1));
            sts32(sb + SMY_MHI + off1, packh2(h2, h3));
            sts32(sb + SMY_MLO + off1, packh2(e2, e3));
        }
    }

#pragma unroll
    for (int it = 0; it < 8; it++) {
        int q = tid + it * 256;
        int j = q >> 4, p4 = q & 15;
        int t = c * 128 + j;
        float4 v = *reinterpret_cast<const float4*>(g_conv + (size_t)t * CONV_DIM + h * 64 + p4 * 4);
        float dtv = g_dt[(size_t)t * H_M + h];
        float e[4] = {v.x * dtv, v.y * dtv, v.z * dtv, v.w * dtv};
        unsigned chj = (unsigned)(j >> 3);
        unsigned bo  = (unsigned)((j & 7) * 2);
#pragma unroll
        for (int k = 0; k < 4; k++) {
            __half hh = __float2half_rn(e[k]);
            __half hl = __float2half_rn(e[k] - __half2float(hh));
            unsigned addr = swz2(p4 * 4 + k, chj) + bo;
            sts16(sb + SMY_HHI + addr, *reinterpret_cast<unsigned short*>(&hh));
            sts16(sb + SMY_HLO + addr, *reinterpret_cast<unsigned short*>(&hl));
        }
    }
    __syncthreads();

    const int wn2 = (wid >> 2) << 5;
    const int brow2 = wn2 + (lane & 15);
    float acc2[2][4][4];
#pragma unroll
    for (int i = 0; i < 2; i++)
#pragma unroll
        for (int j = 0; j < 4; j++)
#pragma unroll
            for (int q = 0; q < 4; q++) acc2[i][j][q] = 0.f;

#pragma unroll
    for (int kc = 0; kc < 8; kc++) {
        int chunk = kc * 2 + chhi;
        unsigned mh[2][4], ml[2][4], hh[2][4], hl[2][4];
#pragma unroll
        for (int mi = 0; mi < 2; mi++) {
            ldsm4(sb + SMY_MHI + swz2(arow + mi * 16, chunk), mh[mi]);
            ldsm4(sb + SMY_MLO + swz2(arow + mi * 16, chunk), ml[mi]);
        }
#pragma unroll
        for (int np = 0; np < 2; np++) {
            ldsm4(sb + SMY_HHI + swz2(brow2 + np * 16, chunk), hh[np]);
            ldsm4(sb + SMY_HLO + swz2(brow2 + np * 16, chunk), hl[np]);
        }
#pragma unroll
        for (int mi = 0; mi < 2; mi++)
#pragma unroll
            for (int ni = 0; ni < 4; ni++) {
                int np = ni >> 1, sr = ni & 1;
                MMA_F16(acc2[mi][ni], mh[mi], hh[np][sr], hh[np][sr + 2]);
            }
#pragma unroll
        for (int mi = 0; mi < 2; mi++)
#pragma unroll
            for (int ni = 0; ni < 4; ni++) {
                int np = ni >> 1, sr = ni & 1;
                MMA_F16(acc2[mi][ni], mh[mi], hl[np][sr], hl[np][sr + 2]);
            }
#pragma unroll
        for (int mi = 0; mi < 2; mi++)
#pragma unroll
            for (int ni = 0; ni < 4; ni++) {
                int np = ni >> 1, sr = ni & 1;
                MMA_F16(acc2[mi][ni], ml[mi], hh[np][sr], hh[np][sr + 2]);
            }
    }

    float dp = Dp[h];
#pragma unroll
    for (int mi = 0; mi < 2; mi++) {
#pragma unroll
        for (int ni = 0; ni < 4; ni++) {
            int r = wm + mi * 16 + (lane >> 2);
            int pc = wn2 + ni * 8 + ((lane & 3) << 1);
            int t0 = c * 128 + r, t1 = t0 + 8;
            float2 hid0 = *reinterpret_cast<const float2*>(g_conv + (size_t)t0 * CONV_DIM + h * 64 + pc);
            float2 hid1 = *reinterpret_cast<const float2*>(g_conv + (size_t)t1 * CONV_DIM + h * 64 + pc);
            float2 o0 = make_float2(acc2[mi][ni][0] + dp * hid0.x, acc2[mi][ni][1] + dp * hid0.y);
            float2 o1 = make_float2(acc2[mi][ni][2] + dp * hid1.x, acc2[mi][ni][3] + dp * hid1.y);
            *reinterpret_cast<float2*>(g_y + (size_t)t0 * D_INNER + h * 64 + pc) = o0;
            *reinterpret_cast<float2*>(g_y + (size_t)t1 * D_INNER + h * 64 + pc) = o1;
        }
    }
}

// ---------------- 1. RMSNorm -> fp16 directly ----------------
__global__ __launch_bounds__(256) void kRms(const float* __restrict__ x,
                                            const float* __restrict__ w) {
    int s = blockIdx.x, tid = threadIdx.x;
    const float* xr = x + (size_t)s * D_MODEL;
    float4 v[4];
    float ss = 0.f;
#pragma unroll
    for (int i = 0; i < 4; i++) {
        v[i] = *reinterpret_cast<const float4*>(xr + tid * 4 + i * 1024);
        ss += v[i].x * v[i].x + v[i].y * v[i].y + v[i].z * v[i].z + v[i].w * v[i].w;
    }
    __shared__ float red[256];
    red[tid] = ss;
    __syncthreads();
    for (int o = 128; o > 0; o >>= 1) { if (tid < o) red[tid] += red[tid + o]; __syncthreads(); }
    float rs = rsqrtf(red[0] / (float)D_MODEL + EPS_F);
    size_t base = (size_t)s * D_MODEL;
#pragma unroll
    for (int i = 0; i < 4; i++) {
        float4 ww = *reinterpret_cast<const float4*>(w + tid * 4 + i * 1024);
        float o0 = v[i].x * rs * ww.x, o1 = v[i].y * rs * ww.y;
        float o2 = v[i].z * rs * ww.z, o3 = v[i].w * rs * ww.w;
        size_t idx = base + tid * 4 + i * 1024;
        *reinterpret_cast<__half2*>(g_ah + idx)     = __floats2half2_rn(o0, o1);
        *reinterpret_cast<__half2*>(g_ah + idx + 2) = __floats2half2_rn(o2, o3);
    }
}

// ---------------- 3. causal conv (k=4) + SiLU, smem-tiled ----------------
#define CONV_T 32
__global__ __launch_bounds__(256) void kConv(const float* __restrict__ cw,
                                             const float* __restrict__ cb) {
    __shared__ float st[CONV_T + 3][256];
    int cb0 = blockIdx.x * 256;
    int t0  = blockIdx.y * CONV_T;
    int tid = threadIdx.x;
    int ch  = cb0 + tid;
#pragma unroll
    for (int i = 0; i < CONV_T + 3; i++) {
        int ti = t0 - 3 + i;
        st[i][tid] = (ti >= 0) ? g_proj[(size_t)ti * PROJ_DIM + D_INNER + ch] : 0.f;
    }
    __syncthreads();
    float w0 = cw[ch * 4 + 0], w1 = cw[ch * 4 + 1];
    float w2 = cw[ch * 4 + 2], w3 = cw[ch * 4 + 3];
    float bias = cb[ch];
#pragma unroll
    for (int k = 0; k < CONV_T; k++) {
        float acc = bias + st[k][tid] * w0 + st[k + 1][tid] * w1
                  + st[k + 2][tid] * w2 + st[k + 3][tid] * w3;
        g_conv[(size_t)(t0 + k) * CONV_DIM + ch] = siluf(acc);
    }
}

// ---------------- 4. dt / a ----------------
__global__ __launch_bounds__(256) void kDt(const float* __restrict__ dtb,
                                           const float* __restrict__ alog) {
    int idx = blockIdx.x * 256 + threadIdx.x;
    int t = idx >> 7, h = idx & 127;
    float v = g_proj[(size_t)t * PROJ_DIM + (D_INNER + CONV_DIM) + h] + dtb[h];
    float dtv = softplusf(v);
    g_dt[idx] = dtv;
    g_a[idx] = -expf(alog[h]) * dtv;
}

// ---------------- 5. cumsum ----------------
__global__ __launch_bounds__(128) void kScan() {
    int b = blockIdx.x;
    int h = b & 127, c = b >> 7;
    int l = threadIdx.x;
    __shared__ float sh[128];
    sh[l] = g_a[(size_t)(c * 128 + l) * H_M + h];
    __syncthreads();
    for (int off = 1; off < 128; off <<= 1) {
        float tv = (l >= off) ? sh[l - off] : 0.f;
        __syncthreads();
        sh[l] += tv;
        __syncthreads();
    }
    g_Acs[(size_t)b * 128 + l] = sh[l];
    if (l == 127) g_cs[b] = sh[127];
}

// ---------------- 8. states (FFMA, known-good) ----------------
__global__ __launch_bounds__(256) void kStates() {
    int h = blockIdx.x, c = blockIdx.y, g = h >> 4;
    __shared__ float hw[32][68];
    __shared__ float Bt[32][132];
    __shared__ float ws[128];
    int tid = threadIdx.x;
    if (tid < 128) {
        float cs = g_cs[c * 128 + h];
        ws[tid] = expf(cs - g_Acs[(size_t)(c * 128 + h) * 128 + tid]);
    }
    __syncthreads();
    int ty = tid >> 4, tx = tid & 15;
    float acc[4][8] = {};
    for (int l0 = 0; l0 < 128; l0 += 32) {
#pragma unroll
        for (int q = tid; q < 512; q += 256) {
            int l = q >> 4;
            int pq = (q & 15) * 4;
            int t = c * 128 + l0 + l;
            float m = g_dt[(size_t)t * H_M + h] * ws[l0 + l];
            float4 v = *reinterpret_cast<const float4*>(g_conv + (size_t)t * CONV_DIM + h * 64 + pq);
            v.x *= m; v.y *= m; v.z *= m; v.w *= m;
            *reinterpret_cast<float4*>(&hw[l][pq]) = v;
        }
#pragma unroll
        for (int q = tid; q < 1024; q += 256) {
            int l = q >> 5;
            int nq = (q & 31) * 4;
            int t = c * 128 + l0 + l;
            float4 v = *reinterpret_cast<const float4*>(g_conv + (size_t)t * CONV_DIM + D_INNER + g * 128 + nq);
            *reinterpret_cast<float4*>(&Bt[l][nq]) = v;
        }
        __syncthreads();
#pragma unroll
        for (int l = 0; l < 32; l++) {
            float4 pv = *reinterpret_cast<float4*>(&hw[l][ty * 4]);
            float rp[4] = {pv.x, pv.y, pv.z, pv.w};
            float rn[8];
            float4 b0 = *reinterpret_cast<float4*>(&Bt[l][tx * 8]);
            float4 b1 = *reinterpret_cast<float4*>(&Bt[l][tx * 8 + 4]);
            rn[0] = b0.x; rn[1] = b0.y; rn[2] = b0.z; rn[3] = b0.w;
            rn[4] = b1.x; rn[5] = b1.y; rn[6] = b1.z; rn[7] = b1.w;
#pragma unroll
            for (int p = 0; p < 4; p++)
#pragma unroll
                for (int n = 0; n < 8; n++) acc[p][n] += rp[p] * rn[n];
        }
        __syncthreads();
    }
    size_t base = ((size_t)(c * 128 + h)) * 8192;
#pragma unroll
    for (int p = 0; p < 4; p++) {
        int pg = ty * 4 + p;
#pragma unroll
        for (int n4 = 0; n4 < 2; n4++) {
            float4 r;
            r.x = acc[p][n4 * 4 + 0]; r.y = acc[p][n4 * 4 + 1];
            r.z = acc[p][n4 * 4 + 2]; r.w = acc[p][n4 * 4 + 3];
            *reinterpret_cast<float4*>(g_states + base + (size_t)pg * 128 + tx * 8 + n4 * 4) = r;
        }
    }
}

// ---------------- 9. recurrence (grid H_M x 8, independent element strips) ----------------
__global__ __launch_bounds__(256) void kRec() {
    int h = blockIdx.x, seg = blockIdx.y * 1024, tid = threadIdx.x;
    float P[4];
#pragma unroll
    for (int k = 0; k < 4; k++) P[k] = 0.f;
    for (int c = 0; c < NCHUNK; c++) {
        size_t base = ((size_t)(c * 128 + h)) * 8192 + seg;
        float ef = expf(g_cs[c * 128 + h]);
#pragma unroll
        for (int k = 0; k < 4; k++) {
            int e = tid + k * 256;
            g_prev[base + e] = P[k];
            P[k] = ef * P[k] + g_states[base + e];
        }
    }
}

// ---------------- 10. Y_off (FFMA, known-good) ----------------
__global__ __launch_bounds__(256) void kYoff() {
    int h = blockIdx.x, c = blockIdx.y, g = h >> 4;
    __shared__ float Cs[32][132];
    __shared__ float Pv[32][68];
    __shared__ float acs[128];
    int tid = threadIdx.x;
    if (tid < 128) acs[tid] = g_Acs[(size_t)(c * 128 + h) * 128 + tid];
    int ty = tid >> 4, tx = tid & 15;
    float acc[8][4] = {};
    const float* Cbase = g_conv + (size_t)(c * 128) * CONV_DIM + D_INNER + GN + g * 128;
    size_t pbase = ((size_t)(c * 128 + h)) * 8192;
    for (int n0 = 0; n0 < 128; n0 += 32) {
#pragma unroll
        for (int q = tid; q < 1024; q += 256) {
            int i = q >> 3;
            int nq = (q & 7) * 4;
            float4 v = *reinterpret_cast<const float4*>(Cbase + (size_t)i * CONV_DIM + n0 + nq);
            Cs[nq + 0][i] = v.x; Cs[nq + 1][i] = v.y; Cs[nq + 2][i] = v.z; Cs[nq + 3][i] = v.w;
        }
#pragma unroll
        for (int q = tid; q < 512; q += 256) {
            int p = q >> 3;
            int nq = (q & 7) * 4;
            float4 v = *reinterpret_cast<const float4*>(g_prev + pbase + (size_t)p * 128 + n0 + nq);
            Pv[nq + 0][p] = v.x; Pv[nq + 1][p] = v.y; Pv[nq + 2][p] = v.z; Pv[nq + 3][p] = v.w;
        }
        __syncthreads();
#pragma unroll
        for (int n = 0; n < 32; n++) {
            float rl[8];
            float4 c0 = *reinterpret_cast<float4*>(&Cs[n][ty * 8]);
            float4 c1 = *reinterpret_cast<float4*>(&Cs[n][ty * 8 + 4]);
            rl[0] = c0.x; rl[1] = c0.y; rl[2] = c0.z; rl[3] = c0.w;
            rl[4] = c1.x; rl[5] = c1.y; rl[6] = c1.z; rl[7] = c1.w;
            float4 pv = *reinterpret_cast<float4*>(&Pv[n][tx * 4]);
            float rp[4] = {pv.x, pv.y, pv.z, pv.w};
#pragma unroll
            for (int i = 0; i < 8; i++)
#pragma unroll
                for (int p = 0; p < 4; p++) acc[i][p] += rl[i] * rp[p];
        }
        __syncthreads();
    }
#pragma unroll
    for (int ii = 0; ii < 8; ii++) {
        int l = ty * 8 + ii;
        int t = c * 128 + l;
        float e = expf(acs[l]);
        float* yp = g_y + (size_t)t * D_INNER + h * 64 + tx * 4;
        float4 cur = *reinterpret_cast<float4*>(yp);
        cur.x += e * acc[ii][0]; cur.y += e * acc[ii][1];
        cur.z += e * acc[ii][2]; cur.w += e * acc[ii][3];
        *reinterpret_cast<float4*>(yp) = cur;
    }
}

// ---------------- 11. gate + group RMSNorm -> fp16 directly ----------------
__global__ __launch_bounds__(256) void kGate(const float* __restrict__ gnw) {
    int b = blockIdx.x;
    int s = b >> 3, g = b & 7;
    int tid = threadIdx.x;
    size_t ybase = (size_t)s * D_INNER + g * 1024;
    size_t pbase = (size_t)s * PROJ_DIM + g * 1024;
    float4 yv = *reinterpret_cast<float4*>(g_y + ybase + tid * 4);
    float4 gv = *reinterpret_cast<const float4*>(g_proj + pbase + tid * 4);
    float4 yg;
    yg.x = yv.x * siluf(gv.x); yg.y = yv.y * siluf(gv.y);
    yg.z = yv.z * siluf(gv.z); yg.w = yv.w * siluf(gv.w);
    float ss = yg.x * yg.x + yg.y * yg.y + yg.z * yg.z + yg.w * yg.w;
    __shared__ float red[256];
    red[tid] = ss;
    __syncthreads();
    for (int o = 128; o > 0; o >>= 1) { if (tid < o) red[tid] += red[tid + o]; __syncthreads(); }
    float rs = rsqrtf(red[0] / 1024.f + EPS_F);
    float4 w = *reinterpret_cast<const float4*>(gnw + g * 1024 + tid * 4);
    float o0 = yg.x * rs * w.x, o1 = yg.y * rs * w.y;
    float o2 = yg.z * rs * w.z, o3 = yg.w * rs * w.w;
    *reinterpret_cast<__half2*>(g_ah + ybase + tid * 4)     = __floats2half2_rn(o0, o1);
    *reinterpret_cast<__half2*>(g_ah + ybase + tid * 4 + 2) = __floats2half2_rn(o2, o3);
}

// ---------------- launch ----------------
extern "C" void kernel_launch(void* const* d_in, const int* in_sizes, int n_in,
                              void* d_out, int out_size) {
    const float* x        = (const float*)d_in[0];
    const float* norm_w   = (const float*)d_in[1];
    const float* in_w     = (const float*)d_in[2];
    const float* conv_w   = (const float*)d_in[3];
    const float* conv_b   = (const float*)d_in[4];
    const float* dt_bias  = (const float*)d_in[5];
    const float* A_log    = (const float*)d_in[6];
    const float* Dp       = (const float*)d_in[7];
    const float* gnorm_w  = (const float*)d_in[8];
    const float* out_w    = (const float*)d_in[9];
    float* out = (float*)d_out;

    cudaFuncSetAttribute(gemm_mma<4096, PROJ_DIM, false>,
                         cudaFuncAttributeMaxDynamicSharedMemorySize, SMEM_MMA);
    cudaFuncSetAttribute(gemm_mma<8192, 4096, true>,
                         cudaFuncAttributeMaxDynamicSharedMemorySize, SMEM_MMA);
    cudaFuncSetAttribute(kMY, cudaFuncAttributeMaxDynamicSharedMemorySize, SMY_TOTAL);

    kRms<<<S_LEN, 256>>>(x, norm_w);
    kCvtW<<<((size_t)PROJ_DIM * 4096) / 2048, 256>>>(in_w);
    gemm_mma<4096, PROJ_DIM, false><<<dim3(S_LEN / 256, PROJ_DIM / 128), 256, SMEM_MMA>>>(nullptr, nullptr);

    kConv<<<dim3(CONV_DIM / 256, S_LEN / CONV_T), 256>>>(conv_w, conv_b);
    kDt<<<(S_LEN * H_M) / 256, 256>>>(dt_bias, A_log);
    kScan<<<NCHUNK * H_M, 128>>>();
    kMY<<<dim3(H_M, NCHUNK), 256, SMY_TOTAL>>>(Dp);
    kStates<<<dim3(H_M, NCHUNK), 256>>>();
    kRec<<<dim3(H_M, 8), 256>>>();
    kYoff<<<dim3(H_M, NCHUNK), 256>>>();
    kGate<<<S_LEN * G_M, 256>>>(gnorm_w);

    kCvtW<<<((size_t)4096 * 8192) / 2048, 256>>>(out_w);
    gemm_mma<8192, 4096, true><<<dim3(S_LEN / 256, 4096 / 128), 256, SMEM_MMA>>>(out, x);
}

// round 16
// speedup vs baseline: 1.0909x; 1.0909x over previous
#include <cuda_runtime.h>
#include <cuda_fp16.h>
#include <math.h>

// ---------------- problem constants ----------------
#define S_LEN   2048
#define D_MODEL 4096
#define H_M     128
#define P_M     64
#define G_M     8
#define N_M     128
#define K_CONV  4
#define CHUNK   128
#define NCHUNK  (S_LEN / CHUNK)          // 16
#define D_INNER (H_M * P_M)              // 8192
#define GN      (G_M * N_M)              // 1024
#define CONV_DIM (D_INNER + 2 * GN)      // 10240
#define PROJ_DIM (D_INNER + CONV_DIM + H_M) // 18560 = 145*128
#define EPS_F   1e-5f

// ---------------- scratch (device globals, no allocation) ----------------
__device__ float g_proj[(size_t)S_LEN * PROJ_DIM];
__device__ float g_conv[(size_t)S_LEN * CONV_DIM];
__device__ float g_dt[(size_t)S_LEN * H_M];
__device__ float g_a[(size_t)S_LEN * H_M];
__device__ float g_Acs[(size_t)NCHUNK * H_M * CHUNK];
__device__ float g_cs[(size_t)NCHUNK * H_M];
__device__ float g_states[(size_t)NCHUNK * H_M * P_M * N_M];
__device__ float g_prev[(size_t)NCHUNK * H_M * P_M * N_M];
__device__ float g_y[(size_t)S_LEN * D_INNER];
// fp16 operands for tensor-core GEMMs: A split hi/lo, W single
__device__ __half g_ah[(size_t)S_LEN * 8192];
__device__ __half g_al[(size_t)S_LEN * 8192];
__device__ __half g_wh[(size_t)PROJ_DIM * 4096];

// ---------------- small helpers ----------------
__device__ __forceinline__ float siluf(float v) { return v / (1.f + expf(-v)); }
__device__ __forceinline__ float softplusf(float v) { return (v > 20.f) ? v : log1pf(expf(v)); }

__device__ __forceinline__ unsigned smem_u32(const void* p) {
    unsigned a;
    asm("{ .reg .u64 t; cvta.to.shared.u64 t, %1; cvt.u32.u64 %0, t; }" : "=r"(a) : "l"(p));
    return a;
}
__device__ __forceinline__ void cpa(unsigned s, const void* g) {
    asm volatile("cp.async.cg.shared.global [%0], [%1], 16;" :: "r"(s), "l"(g));
}
__device__ __forceinline__ void ldsm4(unsigned addr, unsigned* r) {
    asm volatile("ldmatrix.sync.aligned.m8n8.x4.shared.b16 {%0,%1,%2,%3}, [%4];"
                 : "=r"(r[0]), "=r"(r[1]), "=r"(r[2]), "=r"(r[3]) : "r"(addr));
}
#define MMA_F16(acc, a, b0v, b1v)                                              \
    asm volatile("mma.sync.aligned.m16n8k16.row.col.f32.f16.f16.f32 "          \
                 "{%0,%1,%2,%3}, {%4,%5,%6,%7}, {%8,%9}, {%0,%1,%2,%3};"       \
                 : "+f"((acc)[0]), "+f"((acc)[1]), "+f"((acc)[2]), "+f"((acc)[3]) \
                 : "r"((a)[0]), "r"((a)[1]), "r"((a)[2]), "r"((a)[3]),         \
                   "r"(b0v), "r"(b1v))

// swizzled smem byte offset, 64B rows (32 halves)
__device__ __forceinline__ unsigned swz(int row, int c) {
    return (unsigned)(row * 64 + ((c ^ ((row >> 1) & 3)) << 4));
}
// swizzled smem byte offset, 256B rows (128 halves), ch = 16B chunk 0..15
__device__ __forceinline__ unsigned swz2(int row, int ch) {
    return (unsigned)(row * 256 + ((ch ^ (row & 7)) << 4));
}
__device__ __forceinline__ void sts16v(unsigned addr, const unsigned* v) {
    asm volatile("st.shared.v4.b32 [%0], {%1,%2,%3,%4};"
                 :: "r"(addr), "r"(v[0]), "r"(v[1]), "r"(v[2]), "r"(v[3]));
}
__device__ __forceinline__ void sts32(unsigned addr, unsigned v) {
    asm volatile("st.shared.b32 [%0], %1;" :: "r"(addr), "r"(v));
}
__device__ __forceinline__ void sts16(unsigned addr, unsigned short v) {
    asm volatile("st.shared.b16 [%0], %1;" :: "r"(addr), "h"(v));
}
__device__ __forceinline__ unsigned packh2(__half a, __half b) {
    __half2 h = __halves2half2(a, b);
    return *reinterpret_cast<unsigned*>(&h);
}
__device__ __forceinline__ void cvt8(const float* s, unsigned* hi, unsigned* lo) {
#pragma unroll
    for (int k = 0; k < 4; k++) {
        float a = s[2 * k], b = s[2 * k + 1];
        __half ha = __float2half_rn(a), hb = __float2half_rn(b);
        __half la = __float2half_rn(a - __half2float(ha));
        __half lb = __float2half_rn(b - __half2float(hb));
        hi[k] = packh2(ha, hb);
        lo[k] = packh2(la, lb);
    }
}

// ---------------- fp32 -> fp16 weight conversion (8 elem/thread, 16B store) ----------------
__global__ __launch_bounds__(256) void kCvtW(const float* __restrict__ W) {
    size_t idx = ((size_t)blockIdx.x * 256 + threadIdx.x) * 8;
    float4 a = *reinterpret_cast<const float4*>(W + idx);
    float4 b = *reinterpret_cast<const float4*>(W + idx + 4);
    uint4 o;
    o.x = packh2(__float2half_rn(a.x), __float2half_rn(a.y));
    o.y = packh2(__float2half_rn(a.z), __float2half_rn(a.w));
    o.z = packh2(__float2half_rn(b.x), __float2half_rn(b.y));
    o.w = packh2(__float2half_rn(b.z), __float2half_rn(b.w));
    *reinterpret_cast<uint4*>(g_wh + idx) = o;
}

// ---------------- mma.sync GEMM: C[M,N] = A[M,K] * W[N,K]^T (+resid) ----------------
// CTA tile 256x128, 8 warps of 64x64, BK=32, 4-stage cp.async.
// SPLITA: A = Ah + Al 2-term split (in_proj); else single Ah term (out_proj).
template <int KD, int ND, bool OUTPROJ, bool SPLITA>
__global__ __launch_bounds__(256, 1) void gemm_mma(float* __restrict__ outp,
                                                   const float* __restrict__ resid) {
    constexpr unsigned STGB = SPLITA ? 40960u : 24576u;
    constexpr unsigned WOFF = SPLITA ? 32768u : 16384u;
    extern __shared__ char smem[];
    const unsigned sb = smem_u32(smem);
    const int tid = threadIdx.x, lane = tid & 31, wid = tid >> 5;
    const int wm = (wid & 3) << 6;
    const int wn = (wid >> 2) << 6;
    const int row0 = blockIdx.x * 256, col0 = blockIdx.y * 128;
    float* C = OUTPROJ ? outp : g_proj;
    constexpr int NKT = KD / 32;

    float acc[4][8][4];
#pragma unroll
    for (int i = 0; i < 4; i++)
#pragma unroll
        for (int j = 0; j < 8; j++)
#pragma unroll
            for (int q = 0; q < 4; q++) acc[i][j][q] = 0.f;

    const int lr = tid >> 2, lc = tid & 3;
    const __half* gAh = g_ah + (size_t)(row0 + lr) * KD + lc * 8;
    const __half* gAl = g_al + (size_t)(row0 + lr) * KD + lc * 8;
    const __half* gW  = g_wh + (size_t)(col0 + lr) * KD + lc * 8;

    auto issue = [&](int kt) {
        unsigned so = sb + (unsigned)(kt & 3) * STGB;
        size_t ko = (size_t)kt * 32;
#pragma unroll
        for (int j = 0; j < 4; j++) {
            unsigned sw = swz(lr + 64 * j, lc);
            cpa(so + sw, gAh + (size_t)(64 * j) * KD + ko);
            if (SPLITA) cpa(so + 16384u + sw, gAl + (size_t)(64 * j) * KD + ko);
        }
#pragma unroll
        for (int j = 0; j < 2; j++) {
            unsigned sw = swz(lr + 64 * j, lc);
            cpa(so + WOFF + sw, gW + (size_t)(64 * j) * KD + ko);
        }
    };

    issue(0); asm volatile("cp.async.commit_group;" ::: "memory");
    issue(1); asm volatile("cp.async.commit_group;" ::: "memory");
    issue(2); asm volatile("cp.async.commit_group;" ::: "memory");

    const int arow = wm + (lane & 15);
    const int brow = wn + (lane & 15);
    const int chhi = lane >> 4;

    for (int kt = 0; kt < NKT; kt++) {
        asm volatile("cp.async.wait_group 2;" ::: "memory");
        __syncthreads();
        if (kt + 3 < NKT) issue(kt + 3);
        asm volatile("cp.async.commit_group;" ::: "memory");
        unsigned so = sb + (unsigned)(kt & 3) * STGB;
#pragma unroll
        for (int s = 0; s < 2; s++) {
            int chunk = s * 2 + chhi;
            unsigned ah[4][4], al_[4][4], bw[4][4];
#pragma unroll
            for (int mi = 0; mi < 4; mi++) {
                unsigned ad = so + swz(arow + mi * 16, chunk);
                ldsm4(ad, ah[mi]);
                if (SPLITA) ldsm4(ad + 16384u, al_[mi]);
            }
#pragma unroll
            for (int np = 0; np < 4; np++)
                ldsm4(so + WOFF + swz(brow + np * 16, chunk), bw[np]);
#pragma unroll
            for (int mi = 0; mi < 4; mi++)
#pragma unroll
                for (int ni = 0; ni < 8; ni++) {
                    int np = ni >> 1, sr = ni & 1;
                    MMA_F16(acc[mi][ni], ah[mi], bw[np][sr], bw[np][sr + 2]);
                }
            if (SPLITA) {
#pragma unroll
                for (int mi = 0; mi < 4; mi++)
#pragma unroll
                    for (int ni = 0; ni < 8; ni++) {
                        int np = ni >> 1, sr = ni & 1;
                        MMA_F16(acc[mi][ni], al_[mi], bw[np][sr], bw[np][sr + 2]);
                    }
            }
        }
    }

#pragma unroll
    for (int mi = 0; mi < 4; mi++) {
        int r = row0 + wm + mi * 16 + (lane >> 2);
#pragma unroll
        for (int ni = 0; ni < 8; ni++) {
            int c = col0 + wn + ni * 8 + ((lane & 3) << 1);
            float2 v0 = make_float2(acc[mi][ni][0], acc[mi][ni][1]);
            float2 v1 = make_float2(acc[mi][ni][2], acc[mi][ni][3]);
            if (OUTPROJ) {
                const float2 r0 = *reinterpret_cast<const float2*>(resid + (size_t)r * ND + c);
                const float2 r1 = *reinterpret_cast<const float2*>(resid + (size_t)(r + 8) * ND + c);
                v0.x += r0.x; v0.y += r0.y; v1.x += r1.x; v1.y += r1.y;
            }
            *reinterpret_cast<float2*>(C + (size_t)r * ND + c) = v0;
            *reinterpret_cast<float2*>(C + (size_t)(r + 8) * ND + c) = v1;
        }
    }
}

// ---------------- fused M + Y_diag (tensor cores + FMUL-chain L) ----------------
#define SMY_ACS 0u
#define SMY_P   512u
#define SMY_L   1024u
#define SMY_CHI 68608u
#define SMY_CLO (SMY_CHI + 32768u)
#define SMY_BHI (SMY_CLO + 32768u)
#define SMY_BLO (SMY_BHI + 32768u)
#define SMY_TOTAL (SMY_BLO + 32768u)
#define SMY_MHI SMY_CHI
#define SMY_MLO SMY_CLO
#define SMY_HHI SMY_BHI
#define SMY_HLO (SMY_BHI + 16384u)

__global__ __launch_bounds__(256, 1) void kMY(const float* __restrict__ Dp) {
    extern __shared__ char smy[];
    const unsigned sb = smem_u32(smy);
    const int h = blockIdx.x, c = blockIdx.y, g = h >> 4;
    const int tid = threadIdx.x, lane = tid & 31, wid = tid >> 5;

    float* acs  = reinterpret_cast<float*>(smy + SMY_ACS);
    float* pdec = reinterpret_cast<float*>(smy + SMY_P);
    float* Ls   = reinterpret_cast<float*>(smy + SMY_L);

    const float* Cg = g_conv + (size_t)(c * 128) * CONV_DIM + D_INNER + GN + g * 128;
    const float* Bg = g_conv + (size_t)(c * 128) * CONV_DIM + D_INNER + g * 128;
#pragma unroll
    for (int it = 0; it < 8; it++) {
        int q = tid + it * 256;
        int row = q >> 4, ch = q & 15;
        float tmp[8];
        unsigned hi[4], lo[4];
        {
            const float4* cs = reinterpret_cast<const float4*>(Cg + (size_t)row * CONV_DIM + ch * 8);
            float4 a = cs[0], b = cs[1];
            tmp[0]=a.x; tmp[1]=a.y; tmp[2]=a.z; tmp[3]=a.w; tmp[4]=b.x; tmp[5]=b.y; tmp[6]=b.z; tmp[7]=b.w;
            cvt8(tmp, hi, lo);
            sts16v(sb + SMY_CHI + swz2(row, ch), hi);
            sts16v(sb + SMY_CLO + swz2(row, ch), lo);
        }
        {
            const float4* bs = reinterpret_cast<const float4*>(Bg + (size_t)row * CONV_DIM + ch * 8);
            float4 a = bs[0], b = bs[1];
            tmp[0]=a.x; tmp[1]=a.y; tmp[2]=a.z; tmp[3]=a.w; tmp[4]=b.x; tmp[5]=b.y; tmp[6]=b.z; tmp[7]=b.w;
            cvt8(tmp, hi, lo);
            sts16v(sb + SMY_BHI + swz2(row, ch), hi);
            sts16v(sb + SMY_BLO + swz2(row, ch), lo);
        }
    }
    if (tid < 128) {
        acs[tid]  = g_Acs[((size_t)(c * 128 + h)) * 128 + tid];
        pdec[tid] = expf(g_a[(size_t)(c * 128 + tid) * H_M + h]);
    }
    __syncthreads();

    if (tid < 128) {
        int i = tid;
        float* Lr = Ls + i * 132;
        for (int j = i + 1; j < 128; j++) Lr[j] = 0.f;
        float v = 1.f;
        Lr[i] = 1.f;
        for (int j = i - 1; j >= 0; j--) { v *= pdec[j + 1]; Lr[j] = v; }
    }

    const int wm  = (wid & 3) << 5;
    const int wn  = (wid >> 2) << 6;
    const int arow = wm + (lane & 15);
    const int brow = wn + (lane & 15);
    const int chhi = lane >> 4;
    float acc[2][8][4];
#pragma unroll
    for (int i = 0; i < 2; i++)
#pragma unroll
        for (int j = 0; j < 8; j++)
#pragma unroll
            for (int q = 0; q < 4; q++) acc[i][j][q] = 0.f;

#pragma unroll
    for (int kc = 0; kc < 8; kc++) {
        int chunk = kc * 2 + chhi;
        unsigned ah[2][4], al_[2][4], bh[4][4], bl[4][4];
#pragma unroll
        for (int mi = 0; mi < 2; mi++) {
            ldsm4(sb + SMY_CHI + swz2(arow + mi * 16, chunk), ah[mi]);
            ldsm4(sb + SMY_CLO + swz2(arow + mi * 16, chunk), al_[mi]);
        }
#pragma unroll
        for (int np = 0; np < 4; np++) {
            ldsm4(sb + SMY_BHI + swz2(brow + np * 16, chunk), bh[np]);
            ldsm4(sb + SMY_BLO + swz2(brow + np * 16, chunk), bl[np]);
        }
#pragma unroll
        for (int mi = 0; mi < 2; mi++)
#pragma unroll
            for (int ni = 0; ni < 8; ni++) {
                int np = ni >> 1, sr = ni & 1;
                MMA_F16(acc[mi][ni], ah[mi], bh[np][sr], bh[np][sr + 2]);
            }
#pragma unroll
        for (int mi = 0; mi < 2; mi++)
#pragma unroll
            for (int ni = 0; ni < 8; ni++) {
                int np = ni >> 1, sr = ni & 1;
                MMA_F16(acc[mi][ni], ah[mi], bl[np][sr], bl[np][sr + 2]);
            }
#pragma unroll
        for (int mi = 0; mi < 2; mi++)
#pragma unroll
            for (int ni = 0; ni < 8; ni++) {
                int np = ni >> 1, sr = ni & 1;
                MMA_F16(acc[mi][ni], al_[mi], bh[np][sr], bh[np][sr + 2]);
            }
    }
    __syncthreads();

#pragma unroll
    for (int mi = 0; mi < 2; mi++) {
#pragma unroll
        for (int ni = 0; ni < 8; ni++) {
            int r0 = wm + mi * 16 + (lane >> 2);
            int cj = wn + ni * 8 + ((lane & 3) << 1);
            const float* L0 = Ls + r0 * 132 + cj;
            const float* L1 = Ls + (r0 + 8) * 132 + cj;
            float m0 = acc[mi][ni][0] * L0[0];
            float m1 = acc[mi][ni][1] * L0[1];
            float m2 = acc[mi][ni][2] * L1[0];
            float m3 = acc[mi][ni][3] * L1[1];
            __half h0 = __float2half_rn(m0), h1 = __float2half_rn(m1);
            __half h2 = __float2half_rn(m2), h3 = __float2half_rn(m3);
            __half e0 = __float2half_rn(m0 - __half2float(h0));
            __half e1 = __float2half_rn(m1 - __half2float(h1));
            __half e2 = __float2half_rn(m2 - __half2float(h2));
            __half e3 = __float2half_rn(m3 - __half2float(h3));
            unsigned off0 = swz2(r0, cj >> 3) + (cj & 7) * 2;
            unsigned off1 = swz2(r0 + 8, cj >> 3) + (cj & 7) * 2;
            sts32(sb + SMY_MHI + off0, packh2(h0, h1));
            sts32(sb + SMY_MLO + off0, packh2(e0, e1));
            sts32(sb + SMY_MHI + off1, packh2(h2, h3));
            sts32(sb + SMY_MLO + off1, packh2(e2, e3));
        }
    }

#pragma unroll
    for (int it = 0; it < 8; it++) {
        int q = tid + it * 256;
        int j = q >> 4, p4 = q & 15;
        int t = c * 128 + j;
        float4 v = *reinterpret_cast<const float4*>(g_conv + (size_t)t * CONV_DIM + h * 64 + p4 * 4);
        float dtv = g_dt[(size_t)t * H_M + h];
        float e[4] = {v.x * dtv, v.y * dtv, v.z * dtv, v.w * dtv};
        unsigned chj = (unsigned)(j >> 3);
        unsigned bo  = (unsigned)((j & 7) * 2);
#pragma unroll
        for (int k = 0; k < 4; k++) {
            __half hh = __float2half_rn(e[k]);
            __half hl = __float2half_rn(e[k] - __half2float(hh));
            unsigned addr = swz2(p4 * 4 + k, chj) + bo;
            sts16(sb + SMY_HHI + addr, *reinterpret_cast<unsigned short*>(&hh));
            sts16(sb + SMY_HLO + addr, *reinterpret_cast<unsigned short*>(&hl));
        }
    }
    __syncthreads();

    const int wn2 = (wid >> 2) << 5;
    const int brow2 = wn2 + (lane & 15);
    float acc2[2][4][4];
#pragma unroll
    for (int i = 0; i < 2; i++)
#pragma unroll
        for (int j = 0; j < 4; j++)
#pragma unroll
            for (int q = 0; q < 4; q++) acc2[i][j][q] = 0.f;

#pragma unroll
    for (int kc = 0; kc < 8; kc++) {
        int chunk = kc * 2 + chhi;
        unsigned mh[2][4], ml[2][4], hh[2][4], hl[2][4];
#pragma unroll
        for (int mi = 0; mi < 2; mi++) {
            ldsm4(sb + SMY_MHI + swz2(arow + mi * 16, chunk), mh[mi]);
            ldsm4(sb + SMY_MLO + swz2(arow + mi * 16, chunk), ml[mi]);
        }
#pragma unroll
        for (int np = 0; np < 2; np++) {
            ldsm4(sb + SMY_HHI + swz2(brow2 + np * 16, chunk), hh[np]);
            ldsm4(sb + SMY_HLO + swz2(brow2 + np * 16, chunk), hl[np]);
        }
#pragma unroll
        for (int mi = 0; mi < 2; mi++)
#pragma unroll
            for (int ni = 0; ni < 4; ni++) {
                int np = ni >> 1, sr = ni & 1;
                MMA_F16(acc2[mi][ni], mh[mi], hh[np][sr], hh[np][sr + 2]);
            }
#pragma unroll
        for (int mi = 0; mi < 2; mi++)
#pragma unroll
            for (int ni = 0; ni < 4; ni++) {
                int np = ni >> 1, sr = ni & 1;
                MMA_F16(acc2[mi][ni], mh[mi], hl[np][sr], hl[np][sr + 2]);
            }
#pragma unroll
        for (int mi = 0; mi < 2; mi++)
#pragma unroll
            for (int ni = 0; ni < 4; ni++) {
                int np = ni >> 1, sr = ni & 1;
                MMA_F16(acc2[mi][ni], ml[mi], hh[np][sr], hh[np][sr + 2]);
            }
    }

    float dp = Dp[h];
#pragma unroll
    for (int mi = 0; mi < 2; mi++) {
#pragma unroll
        for (int ni = 0; ni < 4; ni++) {
            int r = wm + mi * 16 + (lane >> 2);
            int pc = wn2 + ni * 8 + ((lane & 3) << 1);
            int t0 = c * 128 + r, t1 = t0 + 8;
            float2 hid0 = *reinterpret_cast<const float2*>(g_conv + (size_t)t0 * CONV_DIM + h * 64 + pc);
            float2 hid1 = *reinterpret_cast<const float2*>(g_conv + (size_t)t1 * CONV_DIM + h * 64 + pc);
            float2 o0 = make_float2(acc2[mi][ni][0] + dp * hid0.x, acc2[mi][ni][1] + dp * hid0.y);
            float2 o1 = make_float2(acc2[mi][ni][2] + dp * hid1.x, acc2[mi][ni][3] + dp * hid1.y);
            *reinterpret_cast<float2*>(g_y + (size_t)t0 * D_INNER + h * 64 + pc) = o0;
            *reinterpret_cast<float2*>(g_y + (size_t)t1 * D_INNER + h * 64 + pc) = o1;
        }
    }
}

// ---------------- 1. RMSNorm -> fp16 hi/lo directly ----------------
__global__ __launch_bounds__(256) void kRms(const float* __restrict__ x,
                                            const float* __restrict__ w) {
    int s = blockIdx.x, tid = threadIdx.x;
    const float* xr = x + (size_t)s * D_MODEL;
    float4 v[4];
    float ss = 0.f;
#pragma unroll
    for (int i = 0; i < 4; i++) {
        v[i] = *reinterpret_cast<const float4*>(xr + tid * 4 + i * 1024);
        ss += v[i].x * v[i].x + v[i].y * v[i].y + v[i].z * v[i].z + v[i].w * v[i].w;
    }
    __shared__ float red[256];
    red[tid] = ss;
    __syncthreads();
    for (int o = 128; o > 0; o >>= 1) { if (tid < o) red[tid] += red[tid + o]; __syncthreads(); }
    float rs = rsqrtf(red[0] / (float)D_MODEL + EPS_F);
    size_t base = (size_t)s * D_MODEL;
#pragma unroll
    for (int i = 0; i < 4; i++) {
        float4 ww = *reinterpret_cast<const float4*>(w + tid * 4 + i * 1024);
        float o0 = v[i].x * rs * ww.x, o1 = v[i].y * rs * ww.y;
        float o2 = v[i].z * rs * ww.z, o3 = v[i].w * rs * ww.w;
        __half h0 = __float2half_rn(o0), h1 = __float2half_rn(o1);
        __half h2 = __float2half_rn(o2), h3 = __float2half_rn(o3);
        size_t idx = base + tid * 4 + i * 1024;
        *reinterpret_cast<__half2*>(g_ah + idx)     = __half2(h0, h1);
        *reinterpret_cast<__half2*>(g_ah + idx + 2) = __half2(h2, h3);
        __half l0 = __float2half_rn(o0 - __half2float(h0));
        __half l1 = __float2half_rn(o1 - __half2float(h1));
        __half l2 = __float2half_rn(o2 - __half2float(h2));
        __half l3 = __float2half_rn(o3 - __half2float(h3));
        *reinterpret_cast<__half2*>(g_al + idx)     = __half2(l0, l1);
        *reinterpret_cast<__half2*>(g_al + idx + 2) = __half2(l2, l3);
    }
}

// ---------------- 3. causal conv (k=4) + SiLU, smem-tiled ----------------
#define CONV_T 32
__global__ __launch_bounds__(256) void kConv(const float* __restrict__ cw,
                                             const float* __restrict__ cb) {
    __shared__ float st[CONV_T + 3][256];
    int cb0 = blockIdx.x * 256;
    int t0  = blockIdx.y * CONV_T;
    int tid = threadIdx.x;
    int ch  = cb0 + tid;
#pragma unroll
    for (int i = 0; i < CONV_T + 3; i++) {
        int ti = t0 - 3 + i;
        st[i][tid] = (ti >= 0) ? g_proj[(size_t)ti * PROJ_DIM + D_INNER + ch] : 0.f;
    }
    __syncthreads();
    float w0 = cw[ch * 4 + 0], w1 = cw[ch * 4 + 1];
    float w2 = cw[ch * 4 + 2], w3 = cw[ch * 4 + 3];
    float bias = cb[ch];
#pragma unroll
    for (int k = 0; k < CONV_T; k++) {
        float acc = bias + st[k][tid] * w0 + st[k + 1][tid] * w1
                  + st[k + 2][tid] * w2 + st[k + 3][tid] * w3;
        g_conv[(size_t)(t0 + k) * CONV_DIM + ch] = siluf(acc);
    }
}

// ---------------- 4. dt / a ----------------
__global__ __launch_bounds__(256) void kDt(const float* __restrict__ dtb,
                                           const float* __restrict__ alog) {
    int idx = blockIdx.x * 256 + threadIdx.x;
    int t = idx >> 7, h = idx & 127;
    float v = g_proj[(size_t)t * PROJ_DIM + (D_INNER + CONV_DIM) + h] + dtb[h];
    float dtv = softplusf(v);
    g_dt[idx] = dtv;
    g_a[idx] = -expf(alog[h]) * dtv;
}

// ---------------- 5. cumsum ----------------
__global__ __launch_bounds__(128) void kScan() {
    int b = blockIdx.x;
    int h = b & 127, c = b >> 7;
    int l = threadIdx.x;
    __shared__ float sh[128];
    sh[l] = g_a[(size_t)(c * 128 + l) * H_M + h];
    __syncthreads();
    for (int off = 1; off < 128; off <<= 1) {
        float tv = (l >= off) ? sh[l - off] : 0.f;
        __syncthreads();
        sh[l] += tv;
        __syncthreads();
    }
    g_Acs[(size_t)b * 128 + l] = sh[l];
    if (l == 127) g_cs[b] = sh[127];
}

// ---------------- 8. states (FFMA, known-good) ----------------
__global__ __launch_bounds__(256) void kStates() {
    int h = blockIdx.x, c = blockIdx.y, g = h >> 4;
    __shared__ float hw[32][68];
    __shared__ float Bt[32][132];
    __shared__ float ws[128];
    int tid = threadIdx.x;
    if (tid < 128) {
        float cs = g_cs[c * 128 + h];
        ws[tid] = expf(cs - g_Acs[(size_t)(c * 128 + h) * 128 + tid]);
    }
    __syncthreads();
    int ty = tid >> 4, tx = tid & 15;
    float acc[4][8] = {};
    for (int l0 = 0; l0 < 128; l0 += 32) {
#pragma unroll
        for (int q = tid; q < 512; q += 256) {
            int l = q >> 4;
            int pq = (q & 15) * 4;
            int t = c * 128 + l0 + l;
            float m = g_dt[(size_t)t * H_M + h] * ws[l0 + l];
            float4 v = *reinterpret_cast<const float4*>(g_conv + (size_t)t * CONV_DIM + h * 64 + pq);
            v.x *= m; v.y *= m; v.z *= m; v.w *= m;
            *reinterpret_cast<float4*>(&hw[l][pq]) = v;
        }
#pragma unroll
        for (int q = tid; q < 1024; q += 256) {
            int l = q >> 5;
            int nq = (q & 31) * 4;
            int t = c * 128 + l0 + l;
            float4 v = *reinterpret_cast<const float4*>(g_conv + (size_t)t * CONV_DIM + D_INNER + g * 128 + nq);
            *reinterpret_cast<float4*>(&Bt[l][nq]) = v;
        }
        __syncthreads();
#pragma unroll
        for (int l = 0; l < 32; l++) {
            float4 pv = *reinterpret_cast<float4*>(&hw[l][ty * 4]);
            float rp[4] = {pv.x, pv.y, pv.z, pv.w};
            float rn[8];
            float4 b0 = *reinterpret_cast<float4*>(&Bt[l][tx * 8]);
            float4 b1 = *reinterpret_cast<float4*>(&Bt[l][tx * 8 + 4]);
            rn[0] = b0.x; rn[1] = b0.y; rn[2] = b0.z; rn[3] = b0.w;
            rn[4] = b1.x; rn[5] = b1.y; rn[6] = b1.z; rn[7] = b1.w;
#pragma unroll
            for (int p = 0; p < 4; p++)
#pragma unroll
                for (int n = 0; n < 8; n++) acc[p][n] += rp[p] * rn[n];
        }
        __syncthreads();
    }
    size_t base = ((size_t)(c * 128 + h)) * 8192;
#pragma unroll
    for (int p = 0; p < 4; p++) {
        int pg = ty * 4 + p;
#pragma unroll
        for (int n4 = 0; n4 < 2; n4++) {
            float4 r;
            r.x = acc[p][n4 * 4 + 0]; r.y = acc[p][n4 * 4 + 1];
            r.z = acc[p][n4 * 4 + 2]; r.w = acc[p][n4 * 4 + 3];
            *reinterpret_cast<float4*>(g_states + base + (size_t)pg * 128 + tx * 8 + n4 * 4) = r;
        }
    }
}

// ---------------- 9. recurrence (grid H_M x 8, independent element strips) ----------------
__global__ __launch_bounds__(256) void kRec() {
    int h = blockIdx.x, seg = blockIdx.y * 1024, tid = threadIdx.x;
    float P[4];
#pragma unroll
    for (int k = 0; k < 4; k++) P[k] = 0.f;
    for (int c = 0; c < NCHUNK; c++) {
        size_t base = ((size_t)(c * 128 + h)) * 8192 + seg;
        float ef = expf(g_cs[c * 128 + h]);
#pragma unroll
        for (int k = 0; k < 4; k++) {
            int e = tid + k * 256;
            g_prev[base + e] = P[k];
            P[k] = ef * P[k] + g_states[base + e];
        }
    }
}

// ---------------- 10. Y_off (FFMA, known-good) ----------------
__global__ __launch_bounds__(256) void kYoff() {
    int h = blockIdx.x, c = blockIdx.y, g = h >> 4;
    __shared__ float Cs[32][132];
    __shared__ float Pv[32][68];
    __shared__ float acs[128];
    int tid = threadIdx.x;
    if (tid < 128) acs[tid] = g_Acs[(size_t)(c * 128 + h) * 128 + tid];
    int ty = tid >> 4, tx = tid & 15;
    float acc[8][4] = {};
    const float* Cbase = g_conv + (size_t)(c * 128) * CONV_DIM + D_INNER + GN + g * 128;
    size_t pbase = ((size_t)(c * 128 + h)) * 8192;
    for (int n0 = 0; n0 < 128; n0 += 32) {
#pragma unroll
        for (int q = tid; q < 1024; q += 256) {
            int i = q >> 3;
            int nq = (q & 7) * 4;
            float4 v = *reinterpret_cast<const float4*>(Cbase + (size_t)i * CONV_DIM + n0 + nq);
            Cs[nq + 0][i] = v.x; Cs[nq + 1][i] = v.y; Cs[nq + 2][i] = v.z; Cs[nq + 3][i] = v.w;
        }
#pragma unroll
        for (int q = tid; q < 512; q += 256) {
            int p = q >> 3;
            int nq = (q & 7) * 4;
            float4 v = *reinterpret_cast<const float4*>(g_prev + pbase + (size_t)p * 128 + n0 + nq);
            Pv[nq + 0][p] = v.x; Pv[nq + 1][p] = v.y; Pv[nq + 2][p] = v.z; Pv[nq + 3][p] = v.w;
        }
        __syncthreads();
#pragma unroll
        for (int n = 0; n < 32; n++) {
            float rl[8];
            float4 c0 = *reinterpret_cast<float4*>(&Cs[n][ty * 8]);
            float4 c1 = *reinterpret_cast<float4*>(&Cs[n][ty * 8 + 4]);
            rl[0] = c0.x; rl[1] = c0.y; rl[2] = c0.z; rl[3] = c0.w;
            rl[4] = c1.x; rl[5] = c1.y; rl[6] = c1.z; rl[7] = c1.w;
            float4 pv = *reinterpret_cast<float4*>(&Pv[n][tx * 4]);
            float rp[4] = {pv.x, pv.y, pv.z, pv.w};
#pragma unroll
            for (int i = 0; i < 8; i++)
#pragma unroll
                for (int p = 0; p < 4; p++) acc[i][p] += rl[i] * rp[p];
        }
        __syncthreads();
    }
#pragma unroll
    for (int ii = 0; ii < 8; ii++) {
        int l = ty * 8 + ii;
        int t = c * 128 + l;
        float e = expf(acs[l]);
        float* yp = g_y + (size_t)t * D_INNER + h * 64 + tx * 4;
        float4 cur = *reinterpret_cast<float4*>(yp);
        cur.x += e * acc[ii][0]; cur.y += e * acc[ii][1];
        cur.z += e * acc[ii][2]; cur.w += e * acc[ii][3];
        *reinterpret_cast<float4*>(yp) = cur;
    }
}

// ---------------- 11. gate + group RMSNorm -> fp16 hi directly (out_proj is 1-term) ----------------
__global__ __launch_bounds__(256) void kGate(const float* __restrict__ gnw) {
    int b = blockIdx.x;
    int s = b >> 3, g = b & 7;
    int tid = threadIdx.x;
    size_t ybase = (size_t)s * D_INNER + g * 1024;
    size_t pbase = (size_t)s * PROJ_DIM + g * 1024;
    float4 yv = *reinterpret_cast<float4*>(g_y + ybase + tid * 4);
    float4 gv = *reinterpret_cast<const float4*>(g_proj + pbase + tid * 4);
    float4 yg;
    yg.x = yv.x * siluf(gv.x); yg.y = yv.y * siluf(gv.y);
    yg.z = yv.z * siluf(gv.z); yg.w = yv.w * siluf(gv.w);
    float ss = yg.x * yg.x + yg.y * yg.y + yg.z * yg.z + yg.w * yg.w;
    __shared__ float red[256];
    red[tid] = ss;
    __syncthreads();
    for (int o = 128; o > 0; o >>= 1) { if (tid < o) red[tid] += red[tid + o]; __syncthreads(); }
    float rs = rsqrtf(red[0] / 1024.f + EPS_F);
    float4 w = *reinterpret_cast<const float4*>(gnw + g * 1024 + tid * 4);
    float o0 = yg.x * rs * w.x, o1 = yg.y * rs * w.y;
    float o2 = yg.z * rs * w.z, o3 = yg.w * rs * w.w;
    __half h0 = __float2half_rn(o0), h1 = __float2half_rn(o1);
    __half h2 = __float2half_rn(o2), h3 = __float2half_rn(o3);
    *reinterpret_cast<__half2*>(g_ah + ybase + tid * 4)     = __half2(h0, h1);
    *reinterpret_cast<__half2*>(g_ah + ybase + tid * 4 + 2) = __half2(h2, h3);
}

// ---------------- launch ----------------
extern "C" void kernel_launch(void* const* d_in, const int* in_sizes, int n_in,
                              void* d_out, int out_size) {
    const float* x        = (const float*)d_in[0];
    const float* norm_w   = (const float*)d_in[1];
    const float* in_w     = (const float*)d_in[2];
    const float* conv_w   = (const float*)d_in[3];
    const float* conv_b   = (const float*)d_in[4];
    const float* dt_bias  = (const float*)d_in[5];
    const float* A_log    = (const float*)d_in[6];
    const float* Dp       = (const float*)d_in[7];
    const float* gnorm_w  = (const float*)d_in[8];
    const float* out_w    = (const float*)d_in[9];
    float* out = (float*)d_out;

    cudaFuncSetAttribute(gemm_mma<4096, PROJ_DIM, false, true>,
                         cudaFuncAttributeMaxDynamicSharedMemorySize, 4u * 40960u);
    cudaFuncSetAttribute(gemm_mma<8192, 4096, true, false>,
                         cudaFuncAttributeMaxDynamicSharedMemorySize, 4u * 24576u);
    cudaFuncSetAttribute(kMY, cudaFuncAttributeMaxDynamicSharedMemorySize, SMY_TOTAL);

    kRms<<<S_LEN, 256>>>(x, norm_w);
    kCvtW<<<((size_t)PROJ_DIM * 4096) / 2048, 256>>>(in_w);
    gemm_mma<4096, PROJ_DIM, false, true><<<dim3(S_LEN / 256, PROJ_DIM / 128), 256, 4u * 40960u>>>(nullptr, nullptr);

    kConv<<<dim3(CONV_DIM / 256, S_LEN / CONV_T), 256>>>(conv_w, conv_b);
    kDt<<<(S_LEN * H_M) / 256, 256>>>(dt_bias, A_log);
    kScan<<<NCHUNK * H_M, 128>>>();
    kMY<<<dim3(H_M, NCHUNK), 256, SMY_TOTAL>>>(Dp);
    kStates<<<dim3(H_M, NCHUNK), 256>>>();
    kRec<<<dim3(H_M, 8), 256>>>();
    kYoff<<<dim3(H_M, NCHUNK), 256>>>();
    kGate<<<S_LEN * G_M, 256>>>(gnorm_w);

    kCvtW<<<((size_t)4096 * 8192) / 2048, 256>>>(out_w);
    gemm_mma<8192, 4096, true, false><<<dim3(S_LEN / 256, 4096 / 128), 256, 4u * 24576u>>>(out, x);
}

// round 17
// speedup vs baseline: 1.1013x; 1.0095x over previous
#include <cuda_runtime.h>
#include <cuda_fp16.h>
#include <math.h>

// ---------------- problem constants ----------------
#define S_LEN   2048
#define D_MODEL 4096
#define H_M     128
#define P_M     64
#define G_M     8
#define N_M     128
#define K_CONV  4
#define CHUNK   128
#define NCHUNK  (S_LEN / CHUNK)          // 16
#define D_INNER (H_M * P_M)              // 8192
#define GN      (G_M * N_M)              // 1024
#define CONV_DIM (D_INNER + 2 * GN)      // 10240
#define PROJ_DIM (D_INNER + CONV_DIM + H_M) // 18560 = 145*128
#define EPS_F   1e-5f

// ---------------- scratch (device globals, no allocation) ----------------
__device__ float g_proj[(size_t)S_LEN * PROJ_DIM];
__device__ float g_conv[(size_t)S_LEN * CONV_DIM];
__device__ float g_dt[(size_t)S_LEN * H_M];
__device__ float g_a[(size_t)S_LEN * H_M];
__device__ float g_Acs[(size_t)NCHUNK * H_M * CHUNK];
__device__ float g_cs[(size_t)NCHUNK * H_M];
__device__ float g_states[(size_t)NCHUNK * H_M * P_M * N_M];
__device__ float g_prev[(size_t)NCHUNK * H_M * P_M * N_M];
__device__ float g_y[(size_t)S_LEN * D_INNER];
// fp16 operands for tensor-core GEMMs: A split hi/lo, W single
__device__ __half g_ah[(size_t)S_LEN * 8192];
__device__ __half g_al[(size_t)S_LEN * 8192];
__device__ __half g_wh[(size_t)PROJ_DIM * 4096];

// ---------------- small helpers ----------------
__device__ __forceinline__ float siluf(float v) { return v / (1.f + expf(-v)); }
__device__ __forceinline__ float softplusf(float v) { return (v > 20.f) ? v : log1pf(expf(v)); }

__device__ __forceinline__ unsigned smem_u32(const void* p) {
    unsigned a;
    asm("{ .reg .u64 t; cvta.to.shared.u64 t, %1; cvt.u32.u64 %0, t; }" : "=r"(a) : "l"(p));
    return a;
}
__device__ __forceinline__ void cpa(unsigned s, const void* g) {
    asm volatile("cp.async.cg.shared.global [%0], [%1], 16;" :: "r"(s), "l"(g));
}
__device__ __forceinline__ void ldsm4(unsigned addr, unsigned* r) {
    asm volatile("ldmatrix.sync.aligned.m8n8.x4.shared.b16 {%0,%1,%2,%3}, [%4];"
                 : "=r"(r[0]), "=r"(r[1]), "=r"(r[2]), "=r"(r[3]) : "r"(addr));
}
#define MMA_F16(acc, a, b0v, b1v)                                              \
    asm volatile("mma.sync.aligned.m16n8k16.row.col.f32.f16.f16.f32 "          \
                 "{%0,%1,%2,%3}, {%4,%5,%6,%7}, {%8,%9}, {%0,%1,%2,%3};"       \
                 : "+f"((acc)[0]), "+f"((acc)[1]), "+f"((acc)[2]), "+f"((acc)[3]) \
                 : "r"((a)[0]), "r"((a)[1]), "r"((a)[2]), "r"((a)[3]),         \
                   "r"(b0v), "r"(b1v))

// swizzled smem byte offset, 64B rows (32 halves)
__device__ __forceinline__ unsigned swz(int row, int c) {
    return (unsigned)(row * 64 + ((c ^ ((row >> 1) & 3)) << 4));
}
// swizzled smem byte offset, 256B rows (128 halves), ch = 16B chunk 0..15
__device__ __forceinline__ unsigned swz2(int row, int ch) {
    return (unsigned)(row * 256 + ((ch ^ (row & 7)) << 4));
}
__device__ __forceinline__ void sts16v(unsigned addr, const unsigned* v) {
    asm volatile("st.shared.v4.b32 [%0], {%1,%2,%3,%4};"
                 :: "r"(addr), "r"(v[0]), "r"(v[1]), "r"(v[2]), "r"(v[3]));
}
__device__ __forceinline__ void sts32(unsigned addr, unsigned v) {
    asm volatile("st.shared.b32 [%0], %1;" :: "r"(addr), "r"(v));
}
__device__ __forceinline__ void sts16(unsigned addr, unsigned short v) {
    asm volatile("st.shared.b16 [%0], %1;" :: "r"(addr), "h"(v));
}
__device__ __forceinline__ unsigned packh2(__half a, __half b) {
    __half2 h = __halves2half2(a, b);
    return *reinterpret_cast<unsigned*>(&h);
}
__device__ __forceinline__ void cvt8(const float* s, unsigned* hi, unsigned* lo) {
#pragma unroll
    for (int k = 0; k < 4; k++) {
        float a = s[2 * k], b = s[2 * k + 1];
        __half ha = __float2half_rn(a), hb = __float2half_rn(b);
        __half la = __float2half_rn(a - __half2float(ha));
        __half lb = __float2half_rn(b - __half2float(hb));
        hi[k] = packh2(ha, hb);
        lo[k] = packh2(la, lb);
    }
}

// ---------------- fp32 -> fp16 weight conversion (8 elem/thread, 16B store) ----------------
__global__ __launch_bounds__(256) void kCvtW(const float* __restrict__ W) {
    size_t idx = ((size_t)blockIdx.x * 256 + threadIdx.x) * 8;
    float4 a = *reinterpret_cast<const float4*>(W + idx);
    float4 b = *reinterpret_cast<const float4*>(W + idx + 4);
    uint4 o;
    o.x = packh2(__float2half_rn(a.x), __float2half_rn(a.y));
    o.y = packh2(__float2half_rn(a.z), __float2half_rn(a.w));
    o.z = packh2(__float2half_rn(b.x), __float2half_rn(b.y));
    o.w = packh2(__float2half_rn(b.z), __float2half_rn(b.w));
    *reinterpret_cast<uint4*>(g_wh + idx) = o;
}

// ---------------- mma.sync GEMM: C[M,N] = A[M,K] * W[N,K]^T (+resid) ----------------
// CTA tile 256x128, 8 warps of 64x64, BK=32, 4-stage cp.async.
// SPLITA: A = Ah + Al 2-term split (in_proj); else single Ah term (out_proj).
template <int KD, int ND, bool OUTPROJ, bool SPLITA>
__global__ __launch_bounds__(256, 1) void gemm_mma(float* __restrict__ outp,
                                                   const float* __restrict__ resid) {
    constexpr unsigned STGB = SPLITA ? 40960u : 24576u;
    constexpr unsigned WOFF = SPLITA ? 32768u : 16384u;
    extern __shared__ char smem[];
    const unsigned sb = smem_u32(smem);
    const int tid = threadIdx.x, lane = tid & 31, wid = tid >> 5;
    const int wm = (wid & 3) << 6;
    const int wn = (wid >> 2) << 6;
    const int row0 = blockIdx.x * 256, col0 = blockIdx.y * 128;
    float* C = OUTPROJ ? outp : g_proj;
    constexpr int NKT = KD / 32;

    float acc[4][8][4];
#pragma unroll
    for (int i = 0; i < 4; i++)
#pragma unroll
        for (int j = 0; j < 8; j++)
#pragma unroll
            for (int q = 0; q < 4; q++) acc[i][j][q] = 0.f;

    const int lr = tid >> 2, lc = tid & 3;
    const __half* gAh = g_ah + (size_t)(row0 + lr) * KD + lc * 8;
    const __half* gAl = g_al + (size_t)(row0 + lr) * KD + lc * 8;
    const __half* gW  = g_wh + (size_t)(col0 + lr) * KD + lc * 8;

    auto issue = [&](int kt) {
        unsigned so = sb + (unsigned)(kt & 3) * STGB;
        size_t ko = (size_t)kt * 32;
#pragma unroll
        for (int j = 0; j < 4; j++) {
            unsigned sw = swz(lr + 64 * j, lc);
            cpa(so + sw, gAh + (size_t)(64 * j) * KD + ko);
            if (SPLITA) cpa(so + 16384u + sw, gAl + (size_t)(64 * j) * KD + ko);
        }
#pragma unroll
        for (int j = 0; j < 2; j++) {
            unsigned sw = swz(lr + 64 * j, lc);
            cpa(so + WOFF + sw, gW + (size_t)(64 * j) * KD + ko);
        }
    };

    issue(0); asm volatile("cp.async.commit_group;" ::: "memory");
    issue(1); asm volatile("cp.async.commit_group;" ::: "memory");
    issue(2); asm volatile("cp.async.commit_group;" ::: "memory");

    const int arow = wm + (lane & 15);
    const int brow = wn + (lane & 15);
    const int chhi = lane >> 4;

    for (int kt = 0; kt < NKT; kt++) {
        asm volatile("cp.async.wait_group 2;" ::: "memory");
        __syncthreads();
        if (kt + 3 < NKT) issue(kt + 3);
        asm volatile("cp.async.commit_group;" ::: "memory");
        unsigned so = sb + (unsigned)(kt & 3) * STGB;
#pragma unroll
        for (int s = 0; s < 2; s++) {
            int chunk = s * 2 + chhi;
            unsigned ah[4][4], al_[4][4], bw[4][4];
#pragma unroll
            for (int mi = 0; mi < 4; mi++) {
                unsigned ad = so + swz(arow + mi * 16, chunk);
                ldsm4(ad, ah[mi]);
                if (SPLITA) ldsm4(ad + 16384u, al_[mi]);
            }
#pragma unroll
            for (int np = 0; np < 4; np++)
                ldsm4(so + WOFF + swz(brow + np * 16, chunk), bw[np]);
#pragma unroll
            for (int mi = 0; mi < 4; mi++)
#pragma unroll
                for (int ni = 0; ni < 8; ni++) {
                    int np = ni >> 1, sr = ni & 1;
                    MMA_F16(acc[mi][ni], ah[mi], bw[np][sr], bw[np][sr + 2]);
                }
            if (SPLITA) {
#pragma unroll
                for (int mi = 0; mi < 4; mi++)
#pragma unroll
                    for (int ni = 0; ni < 8; ni++) {
                        int np = ni >> 1, sr = ni & 1;
                        MMA_F16(acc[mi][ni], al_[mi], bw[np][sr], bw[np][sr + 2]);
                    }
            }
        }
    }

#pragma unroll
    for (int mi = 0; mi < 4; mi++) {
        int r = row0 + wm + mi * 16 + (lane >> 2);
#pragma unroll
        for (int ni = 0; ni < 8; ni++) {
            int c = col0 + wn + ni * 8 + ((lane & 3) << 1);
            float2 v0 = make_float2(acc[mi][ni][0], acc[mi][ni][1]);
            float2 v1 = make_float2(acc[mi][ni][2], acc[mi][ni][3]);
            if (OUTPROJ) {
                const float2 r0 = *reinterpret_cast<const float2*>(resid + (size_t)r * ND + c);
                const float2 r1 = *reinterpret_cast<const float2*>(resid + (size_t)(r + 8) * ND + c);
                v0.x += r0.x; v0.y += r0.y; v1.x += r1.x; v1.y += r1.y;
            }
            *reinterpret_cast<float2*>(C + (size_t)r * ND + c) = v0;
            *reinterpret_cast<float2*>(C + (size_t)(r + 8) * ND + c) = v1;
        }
    }
}

// ---------------- fused M + Y_diag (tensor cores + FMUL-chain L) ----------------
#define SMY_ACS 0u
#define SMY_P   512u
#define SMY_L   1024u
#define SMY_CHI 68608u
#define SMY_CLO (SMY_CHI + 32768u)
#define SMY_BHI (SMY_CLO + 32768u)
#define SMY_BLO (SMY_BHI + 32768u)
#define SMY_TOTAL (SMY_BLO + 32768u)
#define SMY_MHI SMY_CHI
#define SMY_MLO SMY_CLO
#define SMY_HHI SMY_BHI
#define SMY_HLO (SMY_BHI + 16384u)

__global__ __launch_bounds__(256, 1) void kMY(const float* __restrict__ Dp) {
    extern __shared__ char smy[];
    const unsigned sb = smem_u32(smy);
    const int h = blockIdx.x, c = blockIdx.y, g = h >> 4;
    const int tid = threadIdx.x, lane = tid & 31, wid = tid >> 5;

    float* acs  = reinterpret_cast<float*>(smy + SMY_ACS);
    float* pdec = reinterpret_cast<float*>(smy + SMY_P);
    float* Ls   = reinterpret_cast<float*>(smy + SMY_L);

    const float* Cg = g_conv + (size_t)(c * 128) * CONV_DIM + D_INNER + GN + g * 128;
    const float* Bg = g_conv + (size_t)(c * 128) * CONV_DIM + D_INNER + g * 128;
#pragma unroll
    for (int it = 0; it < 8; it++) {
        int q = tid + it * 256;
        int row = q >> 4, ch = q & 15;
        float tmp[8];
        unsigned hi[4], lo[4];
        {
            const float4* cs = reinterpret_cast<const float4*>(Cg + (size_t)row * CONV_DIM + ch * 8);
            float4 a = cs[0], b = cs[1];
            tmp[0]=a.x; tmp[1]=a.y; tmp[2]=a.z; tmp[3]=a.w; tmp[4]=b.x; tmp[5]=b.y; tmp[6]=b.z; tmp[7]=b.w;
            cvt8(tmp, hi, lo);
            sts16v(sb + SMY_CHI + swz2(row, ch), hi);
            sts16v(sb + SMY_CLO + swz2(row, ch), lo);
        }
        {
            const float4* bs = reinterpret_cast<const float4*>(Bg + (size_t)row * CONV_DIM + ch * 8);
            float4 a = bs[0], b = bs[1];
            tmp[0]=a.x; tmp[1]=a.y; tmp[2]=a.z; tmp[3]=a.w; tmp[4]=b.x; tmp[5]=b.y; tmp[6]=b.z; tmp[7]=b.w;
            cvt8(tmp, hi, lo);
            sts16v(sb + SMY_BHI + swz2(row, ch), hi);
            sts16v(sb + SMY_BLO + swz2(row, ch), lo);
        }
    }
    if (tid < 128) {
        acs[tid]  = g_Acs[((size_t)(c * 128 + h)) * 128 + tid];
        pdec[tid] = expf(g_a[(size_t)(c * 128 + tid) * H_M + h]);
    }
    __syncthreads();

    if (tid < 128) {
        int i = tid;
        float* Lr = Ls + i * 132;
        for (int j = i + 1; j < 128; j++) Lr[j] = 0.f;
        float v = 1.f;
        Lr[i] = 1.f;
        for (int j = i - 1; j >= 0; j--) { v *= pdec[j + 1]; Lr[j] = v; }
    }

    const int wm  = (wid & 3) << 5;
    const int wn  = (wid >> 2) << 6;
    const int arow = wm + (lane & 15);
    const int brow = wn + (lane & 15);
    const int chhi = lane >> 4;
    float acc[2][8][4];
#pragma unroll
    for (int i = 0; i < 2; i++)
#pragma unroll
        for (int j = 0; j < 8; j++)
#pragma unroll
            for (int q = 0; q < 4; q++) acc[i][j][q] = 0.f;

#pragma unroll
    for (int kc = 0; kc < 8; kc++) {
        int chunk = kc * 2 + chhi;
        unsigned ah[2][4], al_[2][4], bh[4][4], bl[4][4];
#pragma unroll
        for (int mi = 0; mi < 2; mi++) {
            ldsm4(sb + SMY_CHI + swz2(arow + mi * 16, chunk), ah[mi]);
            ldsm4(sb + SMY_CLO + swz2(arow + mi * 16, chunk), al_[mi]);
        }
#pragma unroll
        for (int np = 0; np < 4; np++) {
            ldsm4(sb + SMY_BHI + swz2(brow + np * 16, chunk), bh[np]);
            ldsm4(sb + SMY_BLO + swz2(brow + np * 16, chunk), bl[np]);
        }
#pragma unroll
        for (int mi = 0; mi < 2; mi++)
#pragma unroll
            for (int ni = 0; ni < 8; ni++) {
                int np = ni >> 1, sr = ni & 1;
                MMA_F16(acc[mi][ni], ah[mi], bh[np][sr], bh[np][sr + 2]);
            }
#pragma unroll
        for (int mi = 0; mi < 2; mi++)
#pragma unroll
            for (int ni = 0; ni < 8; ni++) {
                int np = ni >> 1, sr = ni & 1;
                MMA_F16(acc[mi][ni], ah[mi], bl[np][sr], bl[np][sr + 2]);
            }
#pragma unroll
        for (int mi = 0; mi < 2; mi++)
#pragma unroll
            for (int ni = 0; ni < 8; ni++) {
                int np = ni >> 1, sr = ni & 1;
                MMA_F16(acc[mi][ni], al_[mi], bh[np][sr], bh[np][sr + 2]);
            }
    }
    __syncthreads();

#pragma unroll
    for (int mi = 0; mi < 2; mi++) {
#pragma unroll
        for (int ni = 0; ni < 8; ni++) {
            int r0 = wm + mi * 16 + (lane >> 2);
            int cj = wn + ni * 8 + ((lane & 3) << 1);
            const float* L0 = Ls + r0 * 132 + cj;
            const float* L1 = Ls + (r0 + 8) * 132 + cj;
            float m0 = acc[mi][ni][0] * L0[0];
            float m1 = acc[mi][ni][1] * L0[1];
            float m2 = acc[mi][ni][2] * L1[0];
            float m3 = acc[mi][ni][3] * L1[1];
            __half h0 = __float2half_rn(m0), h1 = __float2half_rn(m1);
            __half h2 = __float2half_rn(m2), h3 = __float2half_rn(m3);
            __half e0 = __float2half_rn(m0 - __half2float(h0));
            __half e1 = __float2half_rn(m1 - __half2float(h1));
            __half e2 = __float2half_rn(m2 - __half2float(h2));
            __half e3 = __float2half_rn(m3 - __half2float(h3));
            unsigned off0 = swz2(r0, cj >> 3) + (cj & 7) * 2;
            unsigned off1 = swz2(r0 + 8, cj >> 3) + (cj & 7) * 2;
            sts32(sb + SMY_MHI + off0, packh2(h0, h1));
            sts32(sb + SMY_MLO + off0, packh2(e0, e1));
            sts32(sb + SMY_MHI + off1, packh2(h2, h3));
            sts32(sb + SMY_MLO + off1, packh2(e2, e3));
        }
    }

#pragma unroll
    for (int it = 0; it < 8; it++) {
        int q = tid + it * 256;
        int j = q >> 4, p4 = q & 15;
        int t = c * 128 + j;
        float4 v = *reinterpret_cast<const float4*>(g_conv + (size_t)t * CONV_DIM + h * 64 + p4 * 4);
        float dtv = g_dt[(size_t)t * H_M + h];
        float e[4] = {v.x * dtv, v.y * dtv, v.z * dtv, v.w * dtv};
        unsigned chj = (unsigned)(j >> 3);
        unsigned bo  = (unsigned)((j & 7) * 2);
#pragma unroll
        for (int k = 0; k < 4; k++) {
            __half hh = __float2half_rn(e[k]);
            __half hl = __float2half_rn(e[k] - __half2float(hh));
            unsigned addr = swz2(p4 * 4 + k, chj) + bo;
            sts16(sb + SMY_HHI + addr, *reinterpret_cast<unsigned short*>(&hh));
            sts16(sb + SMY_HLO + addr, *reinterpret_cast<unsigned short*>(&hl));
        }
    }
    __syncthreads();

    const int wn2 = (wid >> 2) << 5;
    const int brow2 = wn2 + (lane & 15);
    float acc2[2][4][4];
#pragma unroll
    for (int i = 0; i < 2; i++)
#pragma unroll
        for (int j = 0; j < 4; j++)
#pragma unroll
            for (int q = 0; q < 4; q++) acc2[i][j][q] = 0.f;

#pragma unroll
    for (int kc = 0; kc < 8; kc++) {
        int chunk = kc * 2 + chhi;
        unsigned mh[2][4], ml[2][4], hh[2][4], hl[2][4];
#pragma unroll
        for (int mi = 0; mi < 2; mi++) {
            ldsm4(sb + SMY_MHI + swz2(arow + mi * 16, chunk), mh[mi]);
            ldsm4(sb + SMY_MLO + swz2(arow + mi * 16, chunk), ml[mi]);
        }
#pragma unroll
        for (int np = 0; np < 2; np++) {
            ldsm4(sb + SMY_HHI + swz2(brow2 + np * 16, chunk), hh[np]);
            ldsm4(sb + SMY_HLO + swz2(brow2 + np * 16, chunk), hl[np]);
        }
#pragma unroll
        for (int mi = 0; mi < 2; mi++)
#pragma unroll
            for (int ni = 0; ni < 4; ni++) {
                int np = ni >> 1, sr = ni & 1;
                MMA_F16(acc2[mi][ni], mh[mi], hh[np][sr], hh[np][sr + 2]);
            }
#pragma unroll
        for (int mi = 0; mi < 2; mi++)
#pragma unroll
            for (int ni = 0; ni < 4; ni++) {
                int np = ni >> 1, sr = ni & 1;
                MMA_F16(acc2[mi][ni], mh[mi], hl[np][sr], hl[np][sr + 2]);
            }
#pragma unroll
        for (int mi = 0; mi < 2; mi++)
#pragma unroll
            for (int ni = 0; ni < 4; ni++) {
                int np = ni >> 1, sr = ni & 1;
                MMA_F16(acc2[mi][ni], ml[mi], hh[np][sr], hh[np][sr + 2]);
            }
    }

    float dp = Dp[h];
#pragma unroll
    for (int mi = 0; mi < 2; mi++) {
#pragma unroll
        for (int ni = 0; ni < 4; ni++) {
            int r = wm + mi * 16 + (lane >> 2);
            int pc = wn2 + ni * 8 + ((lane & 3) << 1);
            int t0 = c * 128 + r, t1 = t0 + 8;
            float2 hid0 = *reinterpret_cast<const float2*>(g_conv + (size_t)t0 * CONV_DIM + h * 64 + pc);
            float2 hid1 = *reinterpret_cast<const float2*>(g_conv + (size_t)t1 * CONV_DIM + h * 64 + pc);
            float2 o0 = make_float2(acc2[mi][ni][0] + dp * hid0.x, acc2[mi][ni][1] + dp * hid0.y);
            float2 o1 = make_float2(acc2[mi][ni][2] + dp * hid1.x, acc2[mi][ni][3] + dp * hid1.y);
            *reinterpret_cast<float2*>(g_y + (size_t)t0 * D_INNER + h * 64 + pc) = o0;
            *reinterpret_cast<float2*>(g_y + (size_t)t1 * D_INNER + h * 64 + pc) = o1;
        }
    }
}

// ---------------- tensor-core Y_off: Y[l][p] += e[l] * sum_n C[l][n]*prev[p][n] ----------------
#define SY_E    0u
#define SY_CHI  1024u
#define SY_CLO  (SY_CHI + 32768u)
#define SY_PHI  (SY_CLO + 32768u)
#define SY_PLO  (SY_PHI + 16384u)
#define SY_TOTAL (SY_PLO + 16384u)   // 99328

__global__ __launch_bounds__(256, 1) void kYoffT() {
    extern __shared__ char sym[];
    const unsigned sb = smem_u32(sym);
    const int h = blockIdx.x, c = blockIdx.y, g = h >> 4;
    const int tid = threadIdx.x, lane = tid & 31, wid = tid >> 5;
    float* eacs = reinterpret_cast<float*>(sym + SY_E);

    if (tid < 128)
        eacs[tid] = expf(g_Acs[((size_t)(c * 128 + h)) * 128 + tid]);

    // C tile (128 l x 128 n), K-major natural, vectorized hi/lo conversion
    const float* Cg = g_conv + (size_t)(c * 128) * CONV_DIM + D_INNER + GN + g * 128;
#pragma unroll
    for (int it = 0; it < 8; it++) {
        int q = tid + it * 256;
        int row = q >> 4, ch = q & 15;
        float tmp[8];
        unsigned hi[4], lo[4];
        const float4* cs = reinterpret_cast<const float4*>(Cg + (size_t)row * CONV_DIM + ch * 8);
        float4 a = cs[0], b = cs[1];
        tmp[0]=a.x; tmp[1]=a.y; tmp[2]=a.z; tmp[3]=a.w; tmp[4]=b.x; tmp[5]=b.y; tmp[6]=b.z; tmp[7]=b.w;
        cvt8(tmp, hi, lo);
        sts16v(sb + SY_CHI + swz2(row, ch), hi);
        sts16v(sb + SY_CLO + swz2(row, ch), lo);
    }
    // prev (64 p x 128 n), already row-major = B operand layout, vectorized conversion
    size_t pbase = ((size_t)(c * 128 + h)) * 8192;
#pragma unroll
    for (int it = 0; it < 4; it++) {
        int q = tid + it * 256;
        int p = q >> 4, ch = q & 15;
        float tmp[8];
        unsigned hi[4], lo[4];
        const float4* ps = reinterpret_cast<const float4*>(g_prev + pbase + (size_t)p * 128 + ch * 8);
        float4 a = ps[0], b = ps[1];
        tmp[0]=a.x; tmp[1]=a.y; tmp[2]=a.z; tmp[3]=a.w; tmp[4]=b.x; tmp[5]=b.y; tmp[6]=b.z; tmp[7]=b.w;
        cvt8(tmp, hi, lo);
        sts16v(sb + SY_PHI + swz2(p, ch), hi);
        sts16v(sb + SY_PLO + swz2(p, ch), lo);
    }
    __syncthreads();

    // GEMM: D[l][p], warps: 4 on l (32 each), 2 on p (32 each)
    const int wm = (wid & 3) << 5;       // l
    const int wn = (wid >> 2) << 5;      // p
    const int arow = wm + (lane & 15);
    const int brow = wn + (lane & 15);
    const int chhi = lane >> 4;
    float acc[2][4][4];
#pragma unroll
    for (int i = 0; i < 2; i++)
#pragma unroll
        for (int j = 0; j < 4; j++)
#pragma unroll
            for (int q = 0; q < 4; q++) acc[i][j][q] = 0.f;

#pragma unroll
    for (int kc = 0; kc < 8; kc++) {
        int chunk = kc * 2 + chhi;
        unsigned ah[2][4], al_[2][4], bh[2][4], bl[2][4];
#pragma unroll
        for (int mi = 0; mi < 2; mi++) {
            ldsm4(sb + SY_CHI + swz2(arow + mi * 16, chunk), ah[mi]);
            ldsm4(sb + SY_CLO + swz2(arow + mi * 16, chunk), al_[mi]);
        }
#pragma unroll
        for (int np = 0; np < 2; np++) {
            ldsm4(sb + SY_PHI + swz2(brow + np * 16, chunk), bh[np]);
            ldsm4(sb + SY_PLO + swz2(brow + np * 16, chunk), bl[np]);
        }
#pragma unroll
        for (int mi = 0; mi < 2; mi++)
#pragma unroll
            for (int ni = 0; ni < 4; ni++) {
                int np = ni >> 1, sr = ni & 1;
                MMA_F16(acc[mi][ni], ah[mi], bh[np][sr], bh[np][sr + 2]);
            }
#pragma unroll
        for (int mi = 0; mi < 2; mi++)
#pragma unroll
            for (int ni = 0; ni < 4; ni++) {
                int np = ni >> 1, sr = ni & 1;
                MMA_F16(acc[mi][ni], ah[mi], bl[np][sr], bl[np][sr + 2]);
            }
#pragma unroll
        for (int mi = 0; mi < 2; mi++)
#pragma unroll
            for (int ni = 0; ni < 4; ni++) {
                int np = ni >> 1, sr = ni & 1;
                MMA_F16(acc[mi][ni], al_[mi], bh[np][sr], bh[np][sr + 2]);
            }
    }

#pragma unroll
    for (int mi = 0; mi < 2; mi++) {
#pragma unroll
        for (int ni = 0; ni < 4; ni++) {
            int l0 = wm + mi * 16 + (lane >> 2);
            int pc = wn + ni * 8 + ((lane & 3) << 1);
            int t0 = c * 128 + l0, t1 = t0 + 8;
            float e0 = eacs[l0], e1 = eacs[l0 + 8];
            float* y0 = g_y + (size_t)t0 * D_INNER + h * 64 + pc;
            float* y1 = g_y + (size_t)t1 * D_INNER + h * 64 + pc;
            float2 c0 = *reinterpret_cast<float2*>(y0);
            float2 c1 = *reinterpret_cast<float2*>(y1);
            c0.x += e0 * acc[mi][ni][0]; c0.y += e0 * acc[mi][ni][1];
            c1.x += e1 * acc[mi][ni][2]; c1.y += e1 * acc[mi][ni][3];
            *reinterpret_cast<float2*>(y0) = c0;
            *reinterpret_cast<float2*>(y1) = c1;
        }
    }
}

// ---------------- 1. RMSNorm -> fp16 hi/lo directly ----------------
__global__ __launch_bounds__(256) void kRms(const float* __restrict__ x,
                                            const float* __restrict__ w) {
    int s = blockIdx.x, tid = threadIdx.x;
    const float* xr = x + (size_t)s * D_MODEL;
    float4 v[4];
    float ss = 0.f;
#pragma unroll
    for (int i = 0; i < 4; i++) {
        v[i] = *reinterpret_cast<const float4*>(xr + tid * 4 + i * 1024);
        ss += v[i].x * v[i].x + v[i].y * v[i].y + v[i].z * v[i].z + v[i].w * v[i].w;
    }
    __shared__ float red[256];
    red[tid] = ss;
    __syncthreads();
    for (int o = 128; o > 0; o >>= 1) { if (tid < o) red[tid] += red[tid + o]; __syncthreads(); }
    float rs = rsqrtf(red[0] / (float)D_MODEL + EPS_F);
    size_t base = (size_t)s * D_MODEL;
#pragma unroll
    for (int i = 0; i < 4; i++) {
        float4 ww = *reinterpret_cast<const float4*>(w + tid * 4 + i * 1024);
        float o0 = v[i].x * rs * ww.x, o1 = v[i].y * rs * ww.y;
        float o2 = v[i].z * rs * ww.z, o3 = v[i].w * rs * ww.w;
        __half h0 = __float2half_rn(o0), h1 = __float2half_rn(o1);
        __half h2 = __float2half_rn(o2), h3 = __float2half_rn(o3);
        size_t idx = base + tid * 4 + i * 1024;
        *reinterpret_cast<__half2*>(g_ah + idx)     = __half2(h0, h1);
        *reinterpret_cast<__half2*>(g_ah + idx + 2) = __half2(h2, h3);
        __half l0 = __float2half_rn(o0 - __half2float(h0));
        __half l1 = __float2half_rn(o1 - __half2float(h1));
        __half l2 = __float2half_rn(o2 - __half2float(h2));
        __half l3 = __float2half_rn(o3 - __half2float(h3));
        *reinterpret_cast<__half2*>(g_al + idx)     = __half2(l0, l1);
        *reinterpret_cast<__half2*>(g_al + idx + 2) = __half2(l2, l3);
    }
}

// ---------------- 3. causal conv (k=4) + SiLU, smem-tiled ----------------
#define CONV_T 32
__global__ __launch_bounds__(256) void kConv(const float* __restrict__ cw,
                                             const float* __restrict__ cb) {
    __shared__ float st[CONV_T + 3][256];
    int cb0 = blockIdx.x * 256;
    int t0  = blockIdx.y * CONV_T;
    int tid = threadIdx.x;
    int ch  = cb0 + tid;
#pragma unroll
    for (int i = 0; i < CONV_T + 3; i++) {
        int ti = t0 - 3 + i;
        st[i][tid] = (ti >= 0) ? g_proj[(size_t)ti * PROJ_DIM + D_INNER + ch] : 0.f;
    }
    __syncthreads();
    float w0 = cw[ch * 4 + 0], w1 = cw[ch * 4 + 1];
    float w2 = cw[ch * 4 + 2], w3 = cw[ch * 4 + 3];
    float bias = cb[ch];
#pragma unroll
    for (int k = 0; k < CONV_T; k++) {
        float acc = bias + st[k][tid] * w0 + st[k + 1][tid] * w1
                  + st[k + 2][tid] * w2 + st[k + 3][tid] * w3;
        g_conv[(size_t)(t0 + k) * CONV_DIM + ch] = siluf(acc);
    }
}

// ---------------- 4. dt / a ----------------
__global__ __launch_bounds__(256) void kDt(const float* __restrict__ dtb,
                                           const float* __restrict__ alog) {
    int idx = blockIdx.x * 256 + threadIdx.x;
    int t = idx >> 7, h = idx & 127;
    float v = g_proj[(size_t)t * PROJ_DIM + (D_INNER + CONV_DIM) + h] + dtb[h];
    float dtv = softplusf(v);
    g_dt[idx] = dtv;
    g_a[idx] = -expf(alog[h]) * dtv;
}

// ---------------- 5. cumsum ----------------
__global__ __launch_bounds__(128) void kScan() {
    int b = blockIdx.x;
    int h = b & 127, c = b >> 7;
    int l = threadIdx.x;
    __shared__ float sh[128];
    sh[l] = g_a[(size_t)(c * 128 + l) * H_M + h];
    __syncthreads();
    for (int off = 1; off < 128; off <<= 1) {
        float tv = (l >= off) ? sh[l - off] : 0.f;
        __syncthreads();
        sh[l] += tv;
        __syncthreads();
    }
    g_Acs[(size_t)b * 128 + l] = sh[l];
    if (l == 127) g_cs[b] = sh[127];
}

// ---------------- 8. states (FFMA, known-good) ----------------
__global__ __launch_bounds__(256) void kStates() {
    int h = blockIdx.x, c = blockIdx.y, g = h >> 4;
    __shared__ float hw[32][68];
    __shared__ float Bt[32][132];
    __shared__ float ws[128];
    int tid = threadIdx.x;
    if (tid < 128) {
        float cs = g_cs[c * 128 + h];
        ws[tid] = expf(cs - g_Acs[(size_t)(c * 128 + h) * 128 + tid]);
    }
    __syncthreads();
    int ty = tid >> 4, tx = tid & 15;
    float acc[4][8] = {};
    for (int l0 = 0; l0 < 128; l0 += 32) {
#pragma unroll
        for (int q = tid; q < 512; q += 256) {
            int l = q >> 4;
            int pq = (q & 15) * 4;
            int t = c * 128 + l0 + l;
            float m = g_dt[(size_t)t * H_M + h] * ws[l0 + l];
            float4 v = *reinterpret_cast<const float4*>(g_conv + (size_t)t * CONV_DIM + h * 64 + pq);
            v.x *= m; v.y *= m; v.z *= m; v.w *= m;
            *reinterpret_cast<float4*>(&hw[l][pq]) = v;
        }
#pragma unroll
        for (int q = tid; q < 1024; q += 256) {
            int l = q >> 5;
            int nq = (q & 31) * 4;
            int t = c * 128 + l0 + l;
            float4 v = *reinterpret_cast<const float4*>(g_conv + (size_t)t * CONV_DIM + D_INNER + g * 128 + nq);
            *reinterpret_cast<float4*>(&Bt[l][nq]) = v;
        }
        __syncthreads();
#pragma unroll
        for (int l = 0; l < 32; l++) {
            float4 pv = *reinterpret_cast<float4*>(&hw[l][ty * 4]);
            float rp[4] = {pv.x, pv.y, pv.z, pv.w};
            float rn[8];
            float4 b0 = *reinterpret_cast<float4*>(&Bt[l][tx * 8]);
            float4 b1 = *reinterpret_cast<float4*>(&Bt[l][tx * 8 + 4]);
            rn[0] = b0.x; rn[1] = b0.y; rn[2] = b0.z; rn[3] = b0.w;
            rn[4] = b1.x; rn[5] = b1.y; rn[6] = b1.z; rn[7] = b1.w;
#pragma unroll
            for (int p = 0; p < 4; p++)
#pragma unroll
                for (int n = 0; n < 8; n++) acc[p][n] += rp[p] * rn[n];
        }
        __syncthreads();
    }
    size_t base = ((size_t)(c * 128 + h)) * 8192;
#pragma unroll
    for (int p = 0; p < 4; p++) {
        int pg = ty * 4 + p;
#pragma unroll
        for (int n4 = 0; n4 < 2; n4++) {
            float4 r;
            r.x = acc[p][n4 * 4 + 0]; r.y = acc[p][n4 * 4 + 1];
            r.z = acc[p][n4 * 4 + 2]; r.w = acc[p][n4 * 4 + 3];
            *reinterpret_cast<float4*>(g_states + base + (size_t)pg * 128 + tx * 8 + n4 * 4) = r;
        }
    }
}

// ---------------- 9. recurrence (grid H_M x 8, independent element strips) ----------------
__global__ __launch_bounds__(256) void kRec() {
    int h = blockIdx.x, seg = blockIdx.y * 1024, tid = threadIdx.x;
    float P[4];
#pragma unroll
    for (int k = 0; k < 4; k++) P[k] = 0.f;
    for (int c = 0; c < NCHUNK; c++) {
        size_t base = ((size_t)(c * 128 + h)) * 8192 + seg;
        float ef = expf(g_cs[c * 128 + h]);
#pragma unroll
        for (int k = 0; k < 4; k++) {
            int e = tid + k * 256;
            g_prev[base + e] = P[k];
            P[k] = ef * P[k] + g_states[base + e];
        }
    }
}

// ---------------- 11. gate + group RMSNorm -> fp16 hi directly (out_proj is 1-term) ----------------
__global__ __launch_bounds__(256) void kGate(const float* __restrict__ gnw) {
    int b = blockIdx.x;
    int s = b >> 3, g = b & 7;
    int tid = threadIdx.x;
    size_t ybase = (size_t)s * D_INNER + g * 1024;
    size_t pbase = (size_t)s * PROJ_DIM + g * 1024;
    float4 yv = *reinterpret_cast<float4*>(g_y + ybase + tid * 4);
    float4 gv = *reinterpret_cast<const float4*>(g_proj + pbase + tid * 4);
    float4 yg;
    yg.x = yv.x * siluf(gv.x); yg.y = yv.y * siluf(gv.y);
    yg.z = yv.z * siluf(gv.z); yg.w = yv.w * siluf(gv.w);
    float ss = yg.x * yg.x + yg.y * yg.y + yg.z * yg.z + yg.w * yg.w;
    __shared__ float red[256];
    red[tid] = ss;
    __syncthreads();
    for (int o = 128; o > 0; o >>= 1) { if (tid < o) red[tid] += red[tid + o]; __syncthreads(); }
    float rs = rsqrtf(red[0] / 1024.f + EPS_F);
    float4 w = *reinterpret_cast<const float4*>(gnw + g * 1024 + tid * 4);
    float o0 = yg.x * rs * w.x, o1 = yg.y * rs * w.y;
    float o2 = yg.z * rs * w.z, o3 = yg.w * rs * w.w;
    __half h0 = __float2half_rn(o0), h1 = __float2half_rn(o1);
    __half h2 = __float2half_rn(o2), h3 = __float2half_rn(o3);
    *reinterpret_cast<__half2*>(g_ah + ybase + tid * 4)     = __half2(h0, h1);
    *reinterpret_cast<__half2*>(g_ah + ybase + tid * 4 + 2) = __half2(h2, h3);
}

// ---------------- launch ----------------
extern "C" void kernel_launch(void* const* d_in, const int* in_sizes, int n_in,
                              void* d_out, int out_size) {
    const float* x        = (const float*)d_in[0];
    const float* norm_w   = (const float*)d_in[1];
    const float* in_w     = (const float*)d_in[2];
    const float* conv_w   = (const float*)d_in[3];
    const float* conv_b   = (const float*)d_in[4];
    const float* dt_bias  = (const float*)d_in[5];
    const float* A_log    = (const float*)d_in[6];
    const float* Dp       = (const float*)d_in[7];
    const float* gnorm_w  = (const float*)d_in[8];
    const float* out_w    = (const float*)d_in[9];
    float* out = (float*)d_out;

    cudaFuncSetAttribute(gemm_mma<4096, PROJ_DIM, false, true>,
                         cudaFuncAttributeMaxDynamicSharedMemorySize, 4u * 40960u);
    cudaFuncSetAttribute(gemm_mma<8192, 4096, true, false>,
                         cudaFuncAttributeMaxDynamicSharedMemorySize, 4u * 24576u);
    cudaFuncSetAttribute(kMY, cudaFuncAttributeMaxDynamicSharedMemorySize, SMY_TOTAL);
    cudaFuncSetAttribute(kYoffT, cudaFuncAttributeMaxDynamicSharedMemorySize, SY_TOTAL);

    kRms<<<S_LEN, 256>>>(x, norm_w);
    kCvtW<<<((size_t)PROJ_DIM * 4096) / 2048, 256>>>(in_w);
    gemm_mma<4096, PROJ_DIM, false, true><<<dim3(S_LEN / 256, PROJ_DIM / 128), 256, 4u * 40960u>>>(nullptr, nullptr);

    kConv<<<dim3(CONV_DIM / 256, S_LEN / CONV_T), 256>>>(conv_w, conv_b);
    kDt<<<(S_LEN * H_M) / 256, 256>>>(dt_bias, A_log);
    kScan<<<NCHUNK * H_M, 128>>>();
    kMY<<<dim3(H_M, NCHUNK), 256, SMY_TOTAL>>>(Dp);
    kStates<<<dim3(H_M, NCHUNK), 256>>>();
    kRec<<<dim3(H_M, 8), 256>>>();
    kYoffT<<<dim3(H_M, NCHUNK), 256, SY_TOTAL>>>();
    kGate<<<S_LEN * G_M, 256>>>(gnorm_w);

    kCvtW<<<((size_t)4096 * 8192) / 2048, 256>>>(out_w);
    gemm_mma<8192, 4096, true, false><<<dim3(S_LEN / 256, 4096 / 128), 256, 4u * 24576u>>>(out, x);
}